// round 6
// baseline (speedup 1.0000x reference)
#include <cuda_runtime.h>
#include <math.h>
#include <stdint.h>

// Problem constants
#define NB 32
#define NS 2048
#define ND 1024

// Scratch (device globals — no allocation allowed)
__device__ float g_dec_proj[NB * ND];                 // 128 KB
__device__ float g_partials[(size_t)NB * NS * 8];     // 2 MB: per-(m, n-tile) partial scores

// ---------------------------------------------------------------------------
// Accurate tanh (immune to --use_fast_math's tanh.approx, whose ~1e-3 rel
// error would blow the error budget after the 1024-wide v-weighted sum).
// ---------------------------------------------------------------------------
__device__ __forceinline__ float tanh_acc(float x) {
    float ax = fabsf(x);
    float e  = __expf(-2.0f * ax);
    float t  = (1.0f - e) / (1.0f + e);
    return copysignf(t, x);
}

// ---------------------------------------------------------------------------
// Kernel 1: dec_proj[b, e] = sum_k dec[b, k] * W_a[e, k]   (Wd = W_a[:, :D])
// grid (32, 8), 256 threads. One warp per output element (coalesced W reads).
// ---------------------------------------------------------------------------
__global__ void k_dec_proj(const float* __restrict__ dec,
                           const float* __restrict__ Wa) {
    __shared__ float ds[ND];
    const int b = blockIdx.x;
    for (int k = threadIdx.x; k < ND; k += blockDim.x)
        ds[k] = dec[b * ND + k];
    __syncthreads();

    const int warp = threadIdx.x >> 5;
    const int lane = threadIdx.x & 31;
    for (int el = warp; el < 128; el += 8) {
        const int e = blockIdx.y * 128 + el;
        const float* w = Wa + (size_t)e * (2 * ND);  // Wd row e (cols [0, D))
        float s = 0.0f;
        for (int k = lane; k < ND; k += 32)
            s = fmaf(ds[k], w[k], s);
        #pragma unroll
        for (int o = 16; o; o >>= 1)
            s += __shfl_xor_sync(0xffffffffu, s, o);
        if (lane == 0)
            g_dec_proj[b * ND + e] = s;
    }
}

// ---------------------------------------------------------------------------
// Kernel 2: fused main GEMM + tanh + v-dot partial reduction.
//   C[m, e] = sum_k enc[m, k] * We[e, k],   We[e,k] = W_a[e*2048 + 1024 + k]
//   partials[m, nblk] = sum_{e in tile} tanh(C[m,e] + dec_proj[b,e]) * v[e]
// Tiles: 128(M) x 128(N) x 16(K), 256 threads, 8x8 microtile, double buffer.
// grid (512, 8). Each M-tile lies inside one batch b (2048 % 128 == 0).
// ---------------------------------------------------------------------------
__global__ __launch_bounds__(256, 2)
void k_gemm_fused(const float* __restrict__ enc,
                  const float* __restrict__ Wa,
                  const float* __restrict__ v) {
    __shared__ float As[2][16][132];   // [buf][k][m], padded
    __shared__ float Bs[2][16][132];   // [buf][k][e], padded

    const int tid = threadIdx.x;
    const int tx  = tid & 15;          // n-thread
    const int ty  = tid >> 4;          // m-thread
    const int m0  = blockIdx.x * 128;
    const int n0  = blockIdx.y * 128;

    // Global-load mapping: 512 float4 per tile per matrix; thread handles
    // rows lrow and lrow+64 at float4-column lk4.
    const int lrow = tid >> 2;          // 0..63
    const int lk4  = (tid & 3) * 4;     // 0,4,8,12

    const float* aP0 = enc + (size_t)(m0 + lrow) * ND + lk4;
    const float* aP1 = aP0 + (size_t)64 * ND;
    const float* bP0 = Wa + (size_t)(n0 + lrow) * (2 * ND) + ND + lk4;  // We
    const float* bP1 = bP0 + (size_t)64 * (2 * ND);

    float acc[8][8];
    #pragma unroll
    for (int i = 0; i < 8; i++)
        #pragma unroll
        for (int j = 0; j < 8; j++)
            acc[i][j] = 0.0f;

    // Prologue: tile 0 -> smem[0]
    {
        float4 a0 = *(const float4*)aP0;
        float4 a1 = *(const float4*)aP1;
        float4 b0 = *(const float4*)bP0;
        float4 b1 = *(const float4*)bP1;
        As[0][lk4 + 0][lrow] = a0.x; As[0][lk4 + 1][lrow] = a0.y;
        As[0][lk4 + 2][lrow] = a0.z; As[0][lk4 + 3][lrow] = a0.w;
        As[0][lk4 + 0][lrow + 64] = a1.x; As[0][lk4 + 1][lrow + 64] = a1.y;
        As[0][lk4 + 2][lrow + 64] = a1.z; As[0][lk4 + 3][lrow + 64] = a1.w;
        Bs[0][lk4 + 0][lrow] = b0.x; Bs[0][lk4 + 1][lrow] = b0.y;
        Bs[0][lk4 + 2][lrow] = b0.z; Bs[0][lk4 + 3][lrow] = b0.w;
        Bs[0][lk4 + 0][lrow + 64] = b1.x; Bs[0][lk4 + 1][lrow + 64] = b1.y;
        Bs[0][lk4 + 2][lrow + 64] = b1.z; Bs[0][lk4 + 3][lrow + 64] = b1.w;
    }
    __syncthreads();

    const int NK = ND / 16;   // 64
    int buf = 0;
    float4 pa0, pa1, pb0, pb1;

    for (int kt = 0; kt < NK; kt++) {
        if (kt + 1 < NK) {
            const int ko = (kt + 1) * 16;
            pa0 = *(const float4*)(aP0 + ko);
            pa1 = *(const float4*)(aP1 + ko);
            pb0 = *(const float4*)(bP0 + ko);
            pb1 = *(const float4*)(bP1 + ko);
        }

        #pragma unroll
        for (int kk = 0; kk < 16; kk++) {
            float4 af0 = *(const float4*)&As[buf][kk][ty * 8];
            float4 af1 = *(const float4*)&As[buf][kk][ty * 8 + 4];
            float4 bf0 = *(const float4*)&Bs[buf][kk][tx * 8];
            float4 bf1 = *(const float4*)&Bs[buf][kk][tx * 8 + 4];
            float a[8] = {af0.x, af0.y, af0.z, af0.w, af1.x, af1.y, af1.z, af1.w};
            float bb[8] = {bf0.x, bf0.y, bf0.z, bf0.w, bf1.x, bf1.y, bf1.z, bf1.w};
            #pragma unroll
            for (int i = 0; i < 8; i++)
                #pragma unroll
                for (int j = 0; j < 8; j++)
                    acc[i][j] = fmaf(a[i], bb[j], acc[i][j]);
        }

        if (kt + 1 < NK) {
            // Safe: smem[buf^1]'s readers passed the sync that ended iter kt-1.
            const int nb = buf ^ 1;
            As[nb][lk4 + 0][lrow] = pa0.x; As[nb][lk4 + 1][lrow] = pa0.y;
            As[nb][lk4 + 2][lrow] = pa0.z; As[nb][lk4 + 3][lrow] = pa0.w;
            As[nb][lk4 + 0][lrow + 64] = pa1.x; As[nb][lk4 + 1][lrow + 64] = pa1.y;
            As[nb][lk4 + 2][lrow + 64] = pa1.z; As[nb][lk4 + 3][lrow + 64] = pa1.w;
            Bs[nb][lk4 + 0][lrow] = pb0.x; Bs[nb][lk4 + 1][lrow] = pb0.y;
            Bs[nb][lk4 + 2][lrow] = pb0.z; Bs[nb][lk4 + 3][lrow] = pb0.w;
            Bs[nb][lk4 + 0][lrow + 64] = pb1.x; Bs[nb][lk4 + 1][lrow + 64] = pb1.y;
            Bs[nb][lk4 + 2][lrow + 64] = pb1.z; Bs[nb][lk4 + 3][lrow + 64] = pb1.w;
            __syncthreads();
            buf = nb;
        }
    }

    // Epilogue: tanh(acc + dec_proj) * v, reduce over the 128 e-columns.
    const int b = m0 >> 11;   // m0 / 2048
    float dvec[8], vv[8];
    #pragma unroll
    for (int j = 0; j < 8; j++) {
        const int e = n0 + tx * 8 + j;
        dvec[j] = g_dec_proj[b * ND + e];
        vv[j]   = v[e];
    }
    float rsum[8];
    #pragma unroll
    for (int i = 0; i < 8; i++) {
        float s = 0.0f;
        #pragma unroll
        for (int j = 0; j < 8; j++)
            s = fmaf(tanh_acc(acc[i][j] + dvec[j]), vv[j], s);
        rsum[i] = s;
    }

    __syncthreads();                 // all mainloop smem reads done
    float* red = &As[0][0][0];       // reuse: need 128*16 = 2048 floats
    #pragma unroll
    for (int i = 0; i < 8; i++)
        red[(ty * 8 + i) * 16 + tx] = rsum[i];
    __syncthreads();

    if (tid < 128) {
        float s = 0.0f;
        #pragma unroll
        for (int t = 0; t < 16; t++)
            s += red[tid * 16 + t];
        g_partials[((size_t)(m0 + tid)) * 8 + blockIdx.y] = s;
    }
}

// ---------------------------------------------------------------------------
// Kernel 3: per-batch softmax over s (sums the 8 n-tile partials first).
// grid 32, 256 threads.
// ---------------------------------------------------------------------------
__global__ void k_softmax(float* __restrict__ out) {
    __shared__ float sc[NS];
    __shared__ float wred[8];
    const int b   = blockIdx.x;
    const int tid = threadIdx.x;
    const int warp = tid >> 5, lane = tid & 31;

    float mx = -1e30f;
    for (int s = tid; s < NS; s += 256) {
        const float* p = &g_partials[((size_t)(b * NS + s)) * 8];
        float t = ((p[0] + p[1]) + (p[2] + p[3])) + ((p[4] + p[5]) + (p[6] + p[7]));
        sc[s] = t;
        mx = fmaxf(mx, t);
    }
    #pragma unroll
    for (int o = 16; o; o >>= 1)
        mx = fmaxf(mx, __shfl_xor_sync(0xffffffffu, mx, o));
    if (lane == 0) wred[warp] = mx;
    __syncthreads();
    if (tid == 0) {
        float m = wred[0];
        #pragma unroll
        for (int i = 1; i < 8; i++) m = fmaxf(m, wred[i]);
        wred[0] = m;
    }
    __syncthreads();
    const float bm = wred[0];
    __syncthreads();   // wred[0] consumed before reuse below

    float sum = 0.0f;
    for (int s = tid; s < NS; s += 256) {
        float e = __expf(sc[s] - bm);
        sc[s] = e;
        sum += e;
    }
    #pragma unroll
    for (int o = 16; o; o >>= 1)
        sum += __shfl_xor_sync(0xffffffffu, sum, o);
    if (lane == 0) wred[warp] = sum;
    __syncthreads();
    if (tid == 0) {
        float t = 0.0f;
        #pragma unroll
        for (int i = 0; i < 8; i++) t += wred[i];
        wred[0] = t;
    }
    __syncthreads();
    const float inv = 1.0f / wred[0];
    for (int s = tid; s < NS; s += 256)
        out[b * NS + s] = sc[s] * inv;
}

// ---------------------------------------------------------------------------
// Launch
// Inputs: [0] decoder_hidden (32*1024), [1] encoder_all_hidden (32*2048*1024),
//         [2] W_a (1024*2048), [3] v (1024). Output: alpha (32*2048) fp32.
// ---------------------------------------------------------------------------
extern "C" void kernel_launch(void* const* d_in, const int* in_sizes, int n_in,
                              void* d_out, int out_size) {
    const float* dec = (const float*)d_in[0];
    const float* enc = (const float*)d_in[1];
    const float* Wa  = (const float*)d_in[2];
    const float* v   = (const float*)d_in[3];
    float* out = (float*)d_out;
    (void)in_sizes; (void)n_in; (void)out_size;

    k_dec_proj<<<dim3(NB, 8), 256>>>(dec, Wa);
    k_gemm_fused<<<dim3(512, 8), 256>>>(enc, Wa, v);
    k_softmax<<<NB, 256>>>(out);
}

// round 8
// speedup vs baseline: 1.9926x; 1.9926x over previous
#include <cuda_runtime.h>
#include <cuda_bf16.h>
#include <math.h>
#include <stdint.h>

// Problem constants
#define NB 32
#define NS 2048
#define ND 1024

// GEMM tiling
#define MT_TILES 512          // 65536 / 128
#define NT_TILES 8            // 1024 / 128
#define NKC 32                // K chunks of 32 (K = 1024)
#define ROW_PITCH 80          // 64B of bf16 data + 16B pad -> conflict-free ldmatrix
#define TILE_SM (128 * ROW_PITCH)            // 10240 B per 128x32 bf16 tile
#define STAGE_BYTES (4 * TILE_SM)            // Ah, Al, Bh, Bl
#define SMEM_GEMM (2 * STAGE_BYTES)          // 81920 B, 2 stages

// ---------------------------------------------------------------------------
// Device scratch (allocation is banned -> __device__ globals)
// Row-major bf16 hi/lo splits, stored as uint4 (8 bf16 per element).
// ---------------------------------------------------------------------------
__device__ float g_dec_proj[NB * ND];                  // 128 KB
__device__ float g_partials[(size_t)NB * NS * 8];      // 2 MB
__device__ __align__(16) uint4 g_enc_hi4[8388608];     // 128 MB  [m][k/8]
__device__ __align__(16) uint4 g_enc_lo4[8388608];     // 128 MB
__device__ __align__(16) uint4 g_We_hi4[131072];       // 2 MB    [e][k/8]
__device__ __align__(16) uint4 g_We_lo4[131072];       // 2 MB

// ---------------------------------------------------------------------------
// PTX helpers (all plain sm_80-era instructions; no 'a'-suffix features)
// ---------------------------------------------------------------------------
__device__ __forceinline__ uint32_t smem_to_u32(const void* p) {
    uint32_t a;
    asm("{ .reg .u64 t; cvta.to.shared.u64 t, %1; cvt.u32.u64 %0, t; }" : "=r"(a) : "l"(p));
    return a;
}
__device__ __forceinline__ void cp_async16(uint32_t dst, const void* src) {
    asm volatile("cp.async.cg.shared.global [%0], [%1], 16;" :: "r"(dst), "l"(src) : "memory");
}
__device__ __forceinline__ void cp_commit() {
    asm volatile("cp.async.commit_group;" ::: "memory");
}
__device__ __forceinline__ void cp_wait1() {
    asm volatile("cp.async.wait_group 1;" ::: "memory");
}
__device__ __forceinline__ void cp_wait0() {
    asm volatile("cp.async.wait_group 0;" ::: "memory");
}
__device__ __forceinline__ void ldmatrix_x4(uint32_t* r, uint32_t addr) {
    asm volatile("ldmatrix.sync.aligned.m8n8.x4.shared.b16 {%0,%1,%2,%3}, [%4];"
        : "=r"(r[0]), "=r"(r[1]), "=r"(r[2]), "=r"(r[3]) : "r"(addr));
}
__device__ __forceinline__ void mma_bf16(float* c, const uint32_t* a, const uint32_t* b) {
    asm volatile(
        "mma.sync.aligned.m16n8k16.row.col.f32.bf16.bf16.f32 "
        "{%0,%1,%2,%3}, {%4,%5,%6,%7}, {%8,%9}, {%0,%1,%2,%3};"
        : "+f"(c[0]), "+f"(c[1]), "+f"(c[2]), "+f"(c[3])
        : "r"(a[0]), "r"(a[1]), "r"(a[2]), "r"(a[3]), "r"(b[0]), "r"(b[1]));
}

// ---------------------------------------------------------------------------
// Accurate tanh (tanh.approx's ~1e-3 error would blow the budget)
// ---------------------------------------------------------------------------
__device__ __forceinline__ float tanh_acc(float x) {
    float ax = fabsf(x);
    float e  = __expf(-2.0f * ax);
    float t  = __fdividef(1.0f - e, 1.0f + e);
    return copysignf(t, x);
}

// ---------------------------------------------------------------------------
// Conversion: fp32 -> exact bf16 hi/lo split, plain row-major.
// ---------------------------------------------------------------------------
__device__ __forceinline__ void split8_store(const float* xs, uint4* hi_dst, uint4* lo_dst) {
    unsigned short hs[8], ls[8];
#pragma unroll
    for (int i = 0; i < 8; i++) {
        __nv_bfloat16 bh = __float2bfloat16_rn(xs[i]);
        float hf = __bfloat162float(bh);
        __nv_bfloat16 bl = __float2bfloat16_rn(xs[i] - hf);
        hs[i] = __bfloat16_as_ushort(bh);
        ls[i] = __bfloat16_as_ushort(bl);
    }
    uint4 H, L;
    H.x = (uint32_t)hs[0] | ((uint32_t)hs[1] << 16);
    H.y = (uint32_t)hs[2] | ((uint32_t)hs[3] << 16);
    H.z = (uint32_t)hs[4] | ((uint32_t)hs[5] << 16);
    H.w = (uint32_t)hs[6] | ((uint32_t)hs[7] << 16);
    L.x = (uint32_t)ls[0] | ((uint32_t)ls[1] << 16);
    L.y = (uint32_t)ls[2] | ((uint32_t)ls[3] << 16);
    L.z = (uint32_t)ls[4] | ((uint32_t)ls[5] << 16);
    L.w = (uint32_t)ls[6] | ((uint32_t)ls[7] << 16);
    *hi_dst = H;
    *lo_dst = L;
}

__global__ void k_convert_enc(const float* __restrict__ enc) {
    size_t t = (size_t)blockIdx.x * blockDim.x + threadIdx.x;   // 8M threads
    const float* p = enc + t * 8;
    float4 x0 = *(const float4*)p;
    float4 x1 = *(const float4*)(p + 4);
    float xs[8] = {x0.x, x0.y, x0.z, x0.w, x1.x, x1.y, x1.z, x1.w};
    split8_store(xs, &g_enc_hi4[t], &g_enc_lo4[t]);
}

__global__ void k_convert_We(const float* __restrict__ Wa) {
    int t  = blockIdx.x * blockDim.x + threadIdx.x;   // 128K threads
    int e  = t >> 7;
    int k0 = (t & 127) * 8;
    const float* p = Wa + (size_t)e * (2 * ND) + ND + k0;   // We[e, k]
    float4 x0 = *(const float4*)p;
    float4 x1 = *(const float4*)(p + 4);
    float xs[8] = {x0.x, x0.y, x0.z, x0.w, x1.x, x1.y, x1.z, x1.w};
    split8_store(xs, &g_We_hi4[t], &g_We_lo4[t]);
}

// ---------------------------------------------------------------------------
// dec_proj[b, e] = sum_k dec[b, k] * W_a[e, k]
// ---------------------------------------------------------------------------
__global__ void k_dec_proj(const float* __restrict__ dec,
                           const float* __restrict__ Wa) {
    __shared__ float ds[ND];
    const int b = blockIdx.x;
    for (int k = threadIdx.x; k < ND; k += blockDim.x)
        ds[k] = dec[b * ND + k];
    __syncthreads();

    const int warp = threadIdx.x >> 5;
    const int lane = threadIdx.x & 31;
    for (int el = warp; el < 128; el += 8) {
        const int e = blockIdx.y * 128 + el;
        const float* w = Wa + (size_t)e * (2 * ND);
        float s = 0.0f;
        for (int k = lane; k < ND; k += 32)
            s = fmaf(ds[k], w[k], s);
#pragma unroll
        for (int o = 16; o; o >>= 1)
            s += __shfl_xor_sync(0xffffffffu, s, o);
        if (lane == 0)
            g_dec_proj[b * ND + e] = s;
    }
}

// ---------------------------------------------------------------------------
// Main GEMM: mma.sync bf16 3-pass split + fused tanh/v epilogue.
// CTA 128(M) x 128(N), K chunks of 32, 2-stage cp.async double buffer.
// 256 threads = 8 warps as 4(m) x 2(n); warp tile 32(M) x 64(N).
// grid (nt=8, mt=512): the 8 nt-CTAs of one mt run together and share A via L2.
// ---------------------------------------------------------------------------
__global__ __launch_bounds__(256, 1)
void k_gemm_tc(const float* __restrict__ v) {
    extern __shared__ __align__(16) char smem[];
    const uint32_t smem_base = smem_to_u32(smem);

    const int tid    = threadIdx.x;
    const int wid    = tid >> 5;
    const int lane   = tid & 31;
    const int warp_m = wid & 3;         // 0..3 -> m offset *32
    const int warp_n = wid >> 2;        // 0..1 -> n offset *64
    const int nt_blk = blockIdx.x;      // 0..7
    const int mt_blk = blockIdx.y;      // 0..511
    const int m0 = mt_blk * 128;
    const int n0 = nt_blk * 128;

    // Global bases (byte pointers), row-major bf16, row = 2048 B
    const char* gAh = (const char*)g_enc_hi4 + (size_t)m0 * 2048;
    const char* gAl = (const char*)g_enc_lo4 + (size_t)m0 * 2048;
    const char* gBh = (const char*)g_We_hi4 + (size_t)n0 * 2048;
    const char* gBl = (const char*)g_We_lo4 + (size_t)n0 * 2048;

    // Per-thread copy slots: 512 16B-chunks per tile, 2 per thread per tile
    const int cid0 = tid, cid1 = tid + 256;
    const int r0c = cid0 >> 2, c0c = (cid0 & 3) * 16;
    const int r1c = cid1 >> 2, c1c = (cid1 & 3) * 16;

    auto load_stage = [&](int stage, int kc) {
        const uint32_t sb = smem_base + stage * STAGE_BYTES;
        const size_t so0 = (size_t)r0c * 2048 + kc * 64 + c0c;
        const size_t so1 = (size_t)r1c * 2048 + kc * 64 + c1c;
        const uint32_t do0 = r0c * ROW_PITCH + c0c;
        const uint32_t do1 = r1c * ROW_PITCH + c1c;
        cp_async16(sb + do0,                 gAh + so0);
        cp_async16(sb + do1,                 gAh + so1);
        cp_async16(sb + TILE_SM + do0,       gAl + so0);
        cp_async16(sb + TILE_SM + do1,       gAl + so1);
        cp_async16(sb + 2 * TILE_SM + do0,   gBh + so0);
        cp_async16(sb + 2 * TILE_SM + do1,   gBh + so1);
        cp_async16(sb + 3 * TILE_SM + do0,   gBl + so0);
        cp_async16(sb + 3 * TILE_SM + do1,   gBl + so1);
    };

    float acc[2][8][4];
#pragma unroll
    for (int mt = 0; mt < 2; mt++)
#pragma unroll
        for (int nt = 0; nt < 8; nt++)
#pragma unroll
            for (int i = 0; i < 4; i++)
                acc[mt][nt][i] = 0.0f;

    // ldmatrix lane-address components (bytes within a tile)
    // A (x4): rows (warp_m*32 + mt*16) + (l%8) + ((l/8)&1)*8, k half +(l/16)*16B
    const uint32_t a_row_l = (uint32_t)((lane & 7) + ((lane >> 3) & 1) * 8);
    const uint32_t a_kh_l  = (uint32_t)((lane >> 4) * 16);
    // B (x4, 2 n-tiles each): n rows (warp_n*64 + q*16) + ((l/16)&1)*8 + (l%8),
    //                         k half +((l/8)&1)*16B
    const uint32_t b_row_l = (uint32_t)(((lane >> 4) & 1) * 8 + (lane & 7));
    const uint32_t b_kh_l  = (uint32_t)(((lane >> 3) & 1) * 16);

    // Prologue
    load_stage(0, 0); cp_commit();
    load_stage(1, 1); cp_commit();

    for (int kc = 0; kc < NKC; kc++) {
        if (kc == NKC - 1) cp_wait0(); else cp_wait1();
        __syncthreads();

        const uint32_t sb = smem_base + (kc & 1) * STAGE_BYTES;
#pragma unroll
        for (int ks = 0; ks < 2; ks++) {
            const uint32_t kso = ks * 32;
            uint32_t aH[2][4], aL[2][4], bH[8][2], bL[8][2];
#pragma unroll
            for (int mt = 0; mt < 2; mt++) {
                const uint32_t rowoff =
                    (uint32_t)(warp_m * 32 + mt * 16) + a_row_l;
                const uint32_t off = rowoff * ROW_PITCH + kso + a_kh_l;
                ldmatrix_x4(aH[mt], sb + off);
                ldmatrix_x4(aL[mt], sb + TILE_SM + off);
            }
#pragma unroll
            for (int q = 0; q < 4; q++) {
                const uint32_t rowoff =
                    (uint32_t)(warp_n * 64 + q * 16) + b_row_l;
                const uint32_t off = rowoff * ROW_PITCH + kso + b_kh_l;
                uint32_t th[4], tl[4];
                ldmatrix_x4(th, sb + 2 * TILE_SM + off);
                ldmatrix_x4(tl, sb + 3 * TILE_SM + off);
                bH[2 * q][0] = th[0]; bH[2 * q][1] = th[1];
                bH[2 * q + 1][0] = th[2]; bH[2 * q + 1][1] = th[3];
                bL[2 * q][0] = tl[0]; bL[2 * q][1] = tl[1];
                bL[2 * q + 1][0] = tl[2]; bL[2 * q + 1][1] = tl[3];
            }
            // 3 passes: Ah*Bh + Ah*Bl + Al*Bh
#pragma unroll
            for (int mt = 0; mt < 2; mt++)
#pragma unroll
                for (int nt = 0; nt < 8; nt++)
                    mma_bf16(acc[mt][nt], aH[mt], bH[nt]);
#pragma unroll
            for (int mt = 0; mt < 2; mt++)
#pragma unroll
                for (int nt = 0; nt < 8; nt++)
                    mma_bf16(acc[mt][nt], aH[mt], bL[nt]);
#pragma unroll
            for (int mt = 0; mt < 2; mt++)
#pragma unroll
                for (int nt = 0; nt < 8; nt++)
                    mma_bf16(acc[mt][nt], aL[mt], bH[nt]);
        }

        __syncthreads();
        if (kc + 2 < NKC) {
            load_stage(kc & 1, kc + 2);
            cp_commit();
        }
    }

    // ----- Fused epilogue: tanh(acc + dec_proj)*v, reduce over n -----
    const int b = m0 >> 11;   // 2048 rows per batch, 128 | 2048
    float dv[16], vv[16];
#pragma unroll
    for (int nt = 0; nt < 8; nt++)
#pragma unroll
        for (int c = 0; c < 2; c++) {
            const int col = n0 + warp_n * 64 + nt * 8 + (lane & 3) * 2 + c;
            dv[nt * 2 + c] = g_dec_proj[b * ND + col];
            vv[nt * 2 + c] = v[col];
        }

    float* red = (float*)smem;    // 128 x 2 floats; safe after last sync below
    __syncthreads();              // everyone done with mainloop smem

#pragma unroll
    for (int mt = 0; mt < 2; mt++)
#pragma unroll
        for (int h = 0; h < 2; h++) {
            float s = 0.0f;
#pragma unroll
            for (int nt = 0; nt < 8; nt++)
#pragma unroll
                for (int c = 0; c < 2; c++)
                    s = fmaf(tanh_acc(acc[mt][nt][h * 2 + c] + dv[nt * 2 + c]),
                             vv[nt * 2 + c], s);
            // reduce across the 4 lanes sharing this row (same lane/4 group)
            s += __shfl_xor_sync(0xffffffffu, s, 1);
            s += __shfl_xor_sync(0xffffffffu, s, 2);
            if ((lane & 3) == 0) {
                const int lr = warp_m * 32 + mt * 16 + h * 8 + (lane >> 2);
                red[lr * 2 + warp_n] = s;
            }
        }
    __syncthreads();

    if (tid < 128)
        g_partials[(size_t)(m0 + tid) * 8 + nt_blk] = red[tid * 2] + red[tid * 2 + 1];
}

// ---------------------------------------------------------------------------
// Per-batch softmax over s
// ---------------------------------------------------------------------------
__global__ void k_softmax(float* __restrict__ out) {
    __shared__ float sc[NS];
    __shared__ float wred[8];
    const int b = blockIdx.x;
    const int tid = threadIdx.x;
    const int warp = tid >> 5, lane = tid & 31;

    float mx = -1e30f;
    for (int s = tid; s < NS; s += 256) {
        const float* p = &g_partials[((size_t)(b * NS + s)) * 8];
        float t = ((p[0] + p[1]) + (p[2] + p[3])) + ((p[4] + p[5]) + (p[6] + p[7]));
        sc[s] = t;
        mx = fmaxf(mx, t);
    }
#pragma unroll
    for (int o = 16; o; o >>= 1)
        mx = fmaxf(mx, __shfl_xor_sync(0xffffffffu, mx, o));
    if (lane == 0) wred[warp] = mx;
    __syncthreads();
    if (tid == 0) {
        float m = wred[0];
#pragma unroll
        for (int i = 1; i < 8; i++) m = fmaxf(m, wred[i]);
        wred[0] = m;
    }
    __syncthreads();
    const float bm = wred[0];
    __syncthreads();

    float sum = 0.0f;
    for (int s = tid; s < NS; s += 256) {
        float e = __expf(sc[s] - bm);
        sc[s] = e;
        sum += e;
    }
#pragma unroll
    for (int o = 16; o; o >>= 1)
        sum += __shfl_xor_sync(0xffffffffu, sum, o);
    if (lane == 0) wred[warp] = sum;
    __syncthreads();
    if (tid == 0) {
        float t = 0.0f;
#pragma unroll
        for (int i = 0; i < 8; i++) t += wred[i];
        wred[0] = t;
    }
    __syncthreads();
    const float inv = 1.0f / wred[0];
    for (int s = tid; s < NS; s += 256)
        out[b * NS + s] = sc[s] * inv;
}

// ---------------------------------------------------------------------------
// Launch
// ---------------------------------------------------------------------------
extern "C" void kernel_launch(void* const* d_in, const int* in_sizes, int n_in,
                              void* d_out, int out_size) {
    const float* dec = (const float*)d_in[0];
    const float* enc = (const float*)d_in[1];
    const float* Wa  = (const float*)d_in[2];
    const float* v   = (const float*)d_in[3];
    float* out = (float*)d_out;
    (void)in_sizes; (void)n_in; (void)out_size;

    cudaFuncSetAttribute(k_gemm_tc, cudaFuncAttributeMaxDynamicSharedMemorySize, SMEM_GEMM);

    k_convert_enc<<<32768, 256>>>(enc);               // 8M threads
    k_convert_We<<<512, 256>>>(Wa);                   // 128K threads
    k_dec_proj<<<dim3(NB, 8), 256>>>(dec, Wa);
    k_gemm_tc<<<dim3(NT_TILES, MT_TILES), 256, SMEM_GEMM>>>(v);
    k_softmax<<<NB, 256>>>(out);
}

// round 9
// speedup vs baseline: 2.0573x; 1.0325x over previous
#include <cuda_runtime.h>
#include <cuda_bf16.h>
#include <math.h>
#include <stdint.h>

// Problem constants
#define NB 32
#define NS 2048
#define ND 1024

// GEMM tiling
#define MT_TILES 512          // 65536 / 128
#define NT_TILES 8            // 1024 / 128
#define NKC 32                // K chunks of 32 (K = 1024)
#define ROW_PITCH 80          // 64B of bf16 data + 16B pad -> conflict-free ldmatrix
#define TILE_SM (128 * ROW_PITCH)            // 10240 B per 128x32 bf16 tile
#define STAGE_BYTES (4 * TILE_SM)            // Ah, Al, Bh, Bl
#define N_STAGES 3
#define SMEM_GEMM (N_STAGES * STAGE_BYTES)   // 122880 B
#define GT 512                               // GEMM threads (16 warps)

// ---------------------------------------------------------------------------
// Device scratch (allocation is banned -> __device__ globals)
// Row-major bf16 hi/lo splits, stored as uint4 (8 bf16 per element).
// ---------------------------------------------------------------------------
__device__ float g_dec_proj[NB * ND];                  // 128 KB
__device__ float g_partials[(size_t)NB * NS * 8];      // 2 MB
__device__ __align__(16) uint4 g_enc_hi4[8388608];     // 128 MB  [m][k/8]
__device__ __align__(16) uint4 g_enc_lo4[8388608];     // 128 MB
__device__ __align__(16) uint4 g_We_hi4[131072];       // 2 MB    [e][k/8]
__device__ __align__(16) uint4 g_We_lo4[131072];       // 2 MB

// ---------------------------------------------------------------------------
// PTX helpers (plain sm_80-era instructions; no 'a'-suffix features)
// ---------------------------------------------------------------------------
__device__ __forceinline__ uint32_t smem_to_u32(const void* p) {
    uint32_t a;
    asm("{ .reg .u64 t; cvta.to.shared.u64 t, %1; cvt.u32.u64 %0, t; }" : "=r"(a) : "l"(p));
    return a;
}
__device__ __forceinline__ void cp_async16(uint32_t dst, const void* src) {
    asm volatile("cp.async.cg.shared.global [%0], [%1], 16;" :: "r"(dst), "l"(src) : "memory");
}
__device__ __forceinline__ void cp_commit() {
    asm volatile("cp.async.commit_group;" ::: "memory");
}
__device__ __forceinline__ void cp_wait1() {
    asm volatile("cp.async.wait_group 1;" ::: "memory");
}
__device__ __forceinline__ void cp_wait0() {
    asm volatile("cp.async.wait_group 0;" ::: "memory");
}
__device__ __forceinline__ void ldmatrix_x4(uint32_t* r, uint32_t addr) {
    asm volatile("ldmatrix.sync.aligned.m8n8.x4.shared.b16 {%0,%1,%2,%3}, [%4];"
        : "=r"(r[0]), "=r"(r[1]), "=r"(r[2]), "=r"(r[3]) : "r"(addr));
}
__device__ __forceinline__ void mma_bf16(float* c, const uint32_t* a, const uint32_t* b) {
    asm volatile(
        "mma.sync.aligned.m16n8k16.row.col.f32.bf16.bf16.f32 "
        "{%0,%1,%2,%3}, {%4,%5,%6,%7}, {%8,%9}, {%0,%1,%2,%3};"
        : "+f"(c[0]), "+f"(c[1]), "+f"(c[2]), "+f"(c[3])
        : "r"(a[0]), "r"(a[1]), "r"(a[2]), "r"(a[3]), "r"(b[0]), "r"(b[1]));
}

// ---------------------------------------------------------------------------
// Accurate tanh (tanh.approx's ~1e-3 error would blow the budget)
// ---------------------------------------------------------------------------
__device__ __forceinline__ float tanh_acc(float x) {
    float ax = fabsf(x);
    float e  = __expf(-2.0f * ax);
    float t  = __fdividef(1.0f - e, 1.0f + e);
    return copysignf(t, x);
}

// ---------------------------------------------------------------------------
// Conversion: fp32 -> exact bf16 hi/lo split, plain row-major.
// ---------------------------------------------------------------------------
__device__ __forceinline__ void split8_store(const float* xs, uint4* hi_dst, uint4* lo_dst) {
    unsigned short hs[8], ls[8];
#pragma unroll
    for (int i = 0; i < 8; i++) {
        __nv_bfloat16 bh = __float2bfloat16_rn(xs[i]);
        float hf = __bfloat162float(bh);
        __nv_bfloat16 bl = __float2bfloat16_rn(xs[i] - hf);
        hs[i] = __bfloat16_as_ushort(bh);
        ls[i] = __bfloat16_as_ushort(bl);
    }
    uint4 H, L;
    H.x = (uint32_t)hs[0] | ((uint32_t)hs[1] << 16);
    H.y = (uint32_t)hs[2] | ((uint32_t)hs[3] << 16);
    H.z = (uint32_t)hs[4] | ((uint32_t)hs[5] << 16);
    H.w = (uint32_t)hs[6] | ((uint32_t)hs[7] << 16);
    L.x = (uint32_t)ls[0] | ((uint32_t)ls[1] << 16);
    L.y = (uint32_t)ls[2] | ((uint32_t)ls[3] << 16);
    L.z = (uint32_t)ls[4] | ((uint32_t)ls[5] << 16);
    L.w = (uint32_t)ls[6] | ((uint32_t)ls[7] << 16);
    *hi_dst = H;
    *lo_dst = L;
}

__global__ void k_convert_enc(const float* __restrict__ enc) {
    size_t t = (size_t)blockIdx.x * blockDim.x + threadIdx.x;   // 8M threads
    const float* p = enc + t * 8;
    float4 x0 = *(const float4*)p;
    float4 x1 = *(const float4*)(p + 4);
    float xs[8] = {x0.x, x0.y, x0.z, x0.w, x1.x, x1.y, x1.z, x1.w};
    split8_store(xs, &g_enc_hi4[t], &g_enc_lo4[t]);
}

__global__ void k_convert_We(const float* __restrict__ Wa) {
    int t  = blockIdx.x * blockDim.x + threadIdx.x;   // 128K threads
    int e  = t >> 7;
    int k0 = (t & 127) * 8;
    const float* p = Wa + (size_t)e * (2 * ND) + ND + k0;   // We[e, k]
    float4 x0 = *(const float4*)p;
    float4 x1 = *(const float4*)(p + 4);
    float xs[8] = {x0.x, x0.y, x0.z, x0.w, x1.x, x1.y, x1.z, x1.w};
    split8_store(xs, &g_We_hi4[t], &g_We_lo4[t]);
}

// ---------------------------------------------------------------------------
// dec_proj[b, e] = sum_k dec[b, k] * W_a[e, k]
// ---------------------------------------------------------------------------
__global__ void k_dec_proj(const float* __restrict__ dec,
                           const float* __restrict__ Wa) {
    __shared__ float ds[ND];
    const int b = blockIdx.x;
    for (int k = threadIdx.x; k < ND; k += blockDim.x)
        ds[k] = dec[b * ND + k];
    __syncthreads();

    const int warp = threadIdx.x >> 5;
    const int lane = threadIdx.x & 31;
    for (int el = warp; el < 128; el += 8) {
        const int e = blockIdx.y * 128 + el;
        const float* w = Wa + (size_t)e * (2 * ND);
        float s = 0.0f;
        for (int k = lane; k < ND; k += 32)
            s = fmaf(ds[k], w[k], s);
#pragma unroll
        for (int o = 16; o; o >>= 1)
            s += __shfl_xor_sync(0xffffffffu, s, o);
        if (lane == 0)
            g_dec_proj[b * ND + e] = s;
    }
}

// ---------------------------------------------------------------------------
// Main GEMM: mma.sync bf16 3-pass split + fused tanh/v epilogue.
// CTA 128(M) x 128(N), K chunks of 32, 3-stage cp.async pipeline.
// 512 threads = 16 warps as 4(m) x 4(n); warp tile 32(M) x 32(N).
// grid (nt=8, mt=512): the 8 nt-CTAs of one mt run together and share A via L2.
// ---------------------------------------------------------------------------
__global__ __launch_bounds__(GT, 1)
void k_gemm_tc(const float* __restrict__ v) {
    extern __shared__ __align__(16) char smem[];
    const uint32_t smem_base = smem_to_u32(smem);

    const int tid    = threadIdx.x;
    const int wid    = tid >> 5;
    const int lane   = tid & 31;
    const int warp_m = wid & 3;         // 0..3 -> m offset *32
    const int warp_n = wid >> 2;        // 0..3 -> n offset *32
    const int nt_blk = blockIdx.x;      // 0..7
    const int mt_blk = blockIdx.y;      // 0..511
    const int m0 = mt_blk * 128;
    const int n0 = nt_blk * 128;

    // Global bases (byte pointers), row-major bf16, row = 2048 B
    const char* gAh = (const char*)g_enc_hi4 + (size_t)m0 * 2048;
    const char* gAl = (const char*)g_enc_lo4 + (size_t)m0 * 2048;
    const char* gBh = (const char*)g_We_hi4 + (size_t)n0 * 2048;
    const char* gBl = (const char*)g_We_lo4 + (size_t)n0 * 2048;

    // Per-thread copy slot: 512 16B-chunks per tile, 1 per thread per tile
    const int rc = tid >> 2;            // 0..127
    const int cc = (tid & 3) * 16;      // 0,16,32,48

    const size_t so_base = (size_t)rc * 2048 + cc;
    const uint32_t do_base = (uint32_t)(rc * ROW_PITCH + cc);

    auto load_stage = [&](int stage, int kc) {
        const uint32_t sb = smem_base + stage * STAGE_BYTES;
        const size_t so = so_base + (size_t)kc * 64;
        cp_async16(sb + do_base,               gAh + so);
        cp_async16(sb + TILE_SM + do_base,     gAl + so);
        cp_async16(sb + 2 * TILE_SM + do_base, gBh + so);
        cp_async16(sb + 3 * TILE_SM + do_base, gBl + so);
    };

    float acc[2][4][4];
#pragma unroll
    for (int mt = 0; mt < 2; mt++)
#pragma unroll
        for (int nt = 0; nt < 4; nt++)
#pragma unroll
            for (int i = 0; i < 4; i++)
                acc[mt][nt][i] = 0.0f;

    // ldmatrix lane-address components (bytes within a tile)
    const uint32_t a_row_l = (uint32_t)((lane & 7) + ((lane >> 3) & 1) * 8);
    const uint32_t a_kh_l  = (uint32_t)((lane >> 4) * 16);
    const uint32_t b_row_l = (uint32_t)(((lane >> 4) & 1) * 8 + (lane & 7));
    const uint32_t b_kh_l  = (uint32_t)(((lane >> 3) & 1) * 16);

    // Prologue: 2 stages in flight
    load_stage(0, 0); cp_commit();
    load_stage(1, 1); cp_commit();

    for (int kc = 0; kc < NKC; kc++) {
        if (kc + 2 < NKC) cp_wait1(); else cp_wait0();
        __syncthreads();

        // Prefetch chunk kc+2 into the stage that held kc-1 (all warps are
        // past compute(kc-1) thanks to the sync above).
        if (kc + 2 < NKC) {
            load_stage((kc + 2) % N_STAGES, kc + 2);
            cp_commit();
        }

        const uint32_t sb = smem_base + (kc % N_STAGES) * STAGE_BYTES;
#pragma unroll
        for (int ks = 0; ks < 2; ks++) {
            const uint32_t kso = ks * 32;
            uint32_t aH[2][4], aL[2][4], bH[4][2], bL[4][2];
#pragma unroll
            for (int mt = 0; mt < 2; mt++) {
                const uint32_t rowoff =
                    (uint32_t)(warp_m * 32 + mt * 16) + a_row_l;
                const uint32_t off = rowoff * ROW_PITCH + kso + a_kh_l;
                ldmatrix_x4(aH[mt], sb + off);
                ldmatrix_x4(aL[mt], sb + TILE_SM + off);
            }
#pragma unroll
            for (int q = 0; q < 2; q++) {
                const uint32_t rowoff =
                    (uint32_t)(warp_n * 32 + q * 16) + b_row_l;
                const uint32_t off = rowoff * ROW_PITCH + kso + b_kh_l;
                uint32_t th[4], tl[4];
                ldmatrix_x4(th, sb + 2 * TILE_SM + off);
                ldmatrix_x4(tl, sb + 3 * TILE_SM + off);
                bH[2 * q][0] = th[0]; bH[2 * q][1] = th[1];
                bH[2 * q + 1][0] = th[2]; bH[2 * q + 1][1] = th[3];
                bL[2 * q][0] = tl[0]; bL[2 * q][1] = tl[1];
                bL[2 * q + 1][0] = tl[2]; bL[2 * q + 1][1] = tl[3];
            }
            // 3 passes: Ah*Bh + Ah*Bl + Al*Bh
#pragma unroll
            for (int mt = 0; mt < 2; mt++)
#pragma unroll
                for (int nt = 0; nt < 4; nt++)
                    mma_bf16(acc[mt][nt], aH[mt], bH[nt]);
#pragma unroll
            for (int mt = 0; mt < 2; mt++)
#pragma unroll
                for (int nt = 0; nt < 4; nt++)
                    mma_bf16(acc[mt][nt], aH[mt], bL[nt]);
#pragma unroll
            for (int mt = 0; mt < 2; mt++)
#pragma unroll
                for (int nt = 0; nt < 4; nt++)
                    mma_bf16(acc[mt][nt], aL[mt], bH[nt]);
        }
    }

    // ----- Fused epilogue: tanh(acc + dec_proj)*v, reduce over n -----
    const int b = m0 >> 11;   // 2048 rows per batch, 128 | 2048
    float dv[8], vv[8];
#pragma unroll
    for (int nt = 0; nt < 4; nt++)
#pragma unroll
        for (int c = 0; c < 2; c++) {
            const int col = n0 + warp_n * 32 + nt * 8 + (lane & 3) * 2 + c;
            dv[nt * 2 + c] = g_dec_proj[b * ND + col];
            vv[nt * 2 + c] = v[col];
        }

    float* red = (float*)smem;    // 128 rows x 4 warp_n floats
    __syncthreads();              // everyone done with mainloop smem

#pragma unroll
    for (int mt = 0; mt < 2; mt++)
#pragma unroll
        for (int h = 0; h < 2; h++) {
            float s = 0.0f;
#pragma unroll
            for (int nt = 0; nt < 4; nt++)
#pragma unroll
                for (int c = 0; c < 2; c++)
                    s = fmaf(tanh_acc(acc[mt][nt][h * 2 + c] + dv[nt * 2 + c]),
                             vv[nt * 2 + c], s);
            // reduce across the 4 lanes sharing this row
            s += __shfl_xor_sync(0xffffffffu, s, 1);
            s += __shfl_xor_sync(0xffffffffu, s, 2);
            if ((lane & 3) == 0) {
                const int lr = warp_m * 32 + mt * 16 + h * 8 + (lane >> 2);
                red[lr * 4 + warp_n] = s;
            }
        }
    __syncthreads();

    if (tid < 128) {
        const float* r = &red[tid * 4];
        g_partials[(size_t)(m0 + tid) * 8 + nt_blk] =
            (r[0] + r[1]) + (r[2] + r[3]);
    }
}

// ---------------------------------------------------------------------------
// Per-batch softmax over s
// ---------------------------------------------------------------------------
__global__ void k_softmax(float* __restrict__ out) {
    __shared__ float sc[NS];
    __shared__ float wred[8];
    const int b = blockIdx.x;
    const int tid = threadIdx.x;
    const int warp = tid >> 5, lane = tid & 31;

    float mx = -1e30f;
    for (int s = tid; s < NS; s += 256) {
        const float* p = &g_partials[((size_t)(b * NS + s)) * 8];
        float t = ((p[0] + p[1]) + (p[2] + p[3])) + ((p[4] + p[5]) + (p[6] + p[7]));
        sc[s] = t;
        mx = fmaxf(mx, t);
    }
#pragma unroll
    for (int o = 16; o; o >>= 1)
        mx = fmaxf(mx, __shfl_xor_sync(0xffffffffu, mx, o));
    if (lane == 0) wred[warp] = mx;
    __syncthreads();
    if (tid == 0) {
        float m = wred[0];
#pragma unroll
        for (int i = 1; i < 8; i++) m = fmaxf(m, wred[i]);
        wred[0] = m;
    }
    __syncthreads();
    const float bm = wred[0];
    __syncthreads();

    float sum = 0.0f;
    for (int s = tid; s < NS; s += 256) {
        float e = __expf(sc[s] - bm);
        sc[s] = e;
        sum += e;
    }
#pragma unroll
    for (int o = 16; o; o >>= 1)
        sum += __shfl_xor_sync(0xffffffffu, sum, o);
    if (lane == 0) wred[warp] = sum;
    __syncthreads();
    if (tid == 0) {
        float t = 0.0f;
#pragma unroll
        for (int i = 0; i < 8; i++) t += wred[i];
        wred[0] = t;
    }
    __syncthreads();
    const float inv = 1.0f / wred[0];
    for (int s = tid; s < NS; s += 256)
        out[b * NS + s] = sc[s] * inv;
}

// ---------------------------------------------------------------------------
// Launch
// ---------------------------------------------------------------------------
extern "C" void kernel_launch(void* const* d_in, const int* in_sizes, int n_in,
                              void* d_out, int out_size) {
    const float* dec = (const float*)d_in[0];
    const float* enc = (const float*)d_in[1];
    const float* Wa  = (const float*)d_in[2];
    const float* v   = (const float*)d_in[3];
    float* out = (float*)d_out;
    (void)in_sizes; (void)n_in; (void)out_size;

    cudaFuncSetAttribute(k_gemm_tc, cudaFuncAttributeMaxDynamicSharedMemorySize, SMEM_GEMM);

    k_convert_enc<<<32768, 256>>>(enc);               // 8M threads
    k_convert_We<<<512, 256>>>(Wa);                   // 128K threads
    k_dec_proj<<<dim3(NB, 8), 256>>>(dec, Wa);
    k_gemm_tc<<<dim3(NT_TILES, MT_TILES), GT, SMEM_GEMM>>>(v);
    k_softmax<<<NB, 256>>>(out);
}

// round 10
// speedup vs baseline: 2.2845x; 1.1104x over previous
#include <cuda_runtime.h>
#include <cuda_bf16.h>
#include <math.h>
#include <stdint.h>

// Problem constants
#define NB 32
#define NS 2048
#define ND 1024

// GEMM tiling: CTA 128(M) x 256(N), K chunks of 32
#define MT_TILES 512          // 65536 / 128
#define NT_TILES 4            // 1024 / 256
#define NKC 32                // K chunks of 32 (K = 1024)
#define ROW_PITCH 80          // 64B bf16 data + 16B pad -> conflict-free ldmatrix
#define TILE_A (128 * ROW_PITCH)             // 10240 B (128 x 32 bf16)
#define TILE_B (256 * ROW_PITCH)             // 20480 B (256 x 32 bf16)
#define STAGE_BYTES (2 * TILE_A + 2 * TILE_B)  // Ah, Al, Bh, Bl = 61440
#define N_STAGES 3
#define SMEM_GEMM (N_STAGES * STAGE_BYTES)   // 184320 B
#define GT 512                               // 16 warps

// ---------------------------------------------------------------------------
// Device scratch (allocation is banned -> __device__ globals)
// ---------------------------------------------------------------------------
__device__ float g_dec_proj[NB * ND];                  // 128 KB
__device__ float g_partials[(size_t)NB * NS * 4];      // 1 MB
__device__ __align__(16) uint4 g_enc_hi4[8388608];     // 128 MB  [m][k/8]
__device__ __align__(16) uint4 g_enc_lo4[8388608];     // 128 MB
__device__ __align__(16) uint4 g_We_hi4[131072];       // 2 MB    [e][k/8]
__device__ __align__(16) uint4 g_We_lo4[131072];       // 2 MB

// ---------------------------------------------------------------------------
// PTX helpers (plain sm_80-era instructions; no 'a'-suffix features)
// ---------------------------------------------------------------------------
__device__ __forceinline__ uint32_t smem_to_u32(const void* p) {
    uint32_t a;
    asm("{ .reg .u64 t; cvta.to.shared.u64 t, %1; cvt.u32.u64 %0, t; }" : "=r"(a) : "l"(p));
    return a;
}
__device__ __forceinline__ void cp_async16(uint32_t dst, const void* src) {
    asm volatile("cp.async.cg.shared.global [%0], [%1], 16;" :: "r"(dst), "l"(src) : "memory");
}
__device__ __forceinline__ void cp_commit() {
    asm volatile("cp.async.commit_group;" ::: "memory");
}
__device__ __forceinline__ void cp_wait1() {
    asm volatile("cp.async.wait_group 1;" ::: "memory");
}
__device__ __forceinline__ void cp_wait0() {
    asm volatile("cp.async.wait_group 0;" ::: "memory");
}
__device__ __forceinline__ void ldmatrix_x4(uint32_t* r, uint32_t addr) {
    asm volatile("ldmatrix.sync.aligned.m8n8.x4.shared.b16 {%0,%1,%2,%3}, [%4];"
        : "=r"(r[0]), "=r"(r[1]), "=r"(r[2]), "=r"(r[3]) : "r"(addr));
}
__device__ __forceinline__ void mma_bf16(float* c, const uint32_t* a, const uint32_t* b) {
    asm volatile(
        "mma.sync.aligned.m16n8k16.row.col.f32.bf16.bf16.f32 "
        "{%0,%1,%2,%3}, {%4,%5,%6,%7}, {%8,%9}, {%0,%1,%2,%3};"
        : "+f"(c[0]), "+f"(c[1]), "+f"(c[2]), "+f"(c[3])
        : "r"(a[0]), "r"(a[1]), "r"(a[2]), "r"(a[3]), "r"(b[0]), "r"(b[1]));
}

// ---------------------------------------------------------------------------
// Accurate tanh (tanh.approx's ~1e-3 error would blow the budget)
// ---------------------------------------------------------------------------
__device__ __forceinline__ float tanh_acc(float x) {
    float ax = fabsf(x);
    float e  = __expf(-2.0f * ax);
    float t  = __fdividef(1.0f - e, 1.0f + e);
    return copysignf(t, x);
}

// ---------------------------------------------------------------------------
// Conversion: fp32 -> exact bf16 hi/lo split, plain row-major.
// ---------------------------------------------------------------------------
__device__ __forceinline__ void split8_store(const float* xs, uint4* hi_dst, uint4* lo_dst) {
    unsigned short hs[8], ls[8];
#pragma unroll
    for (int i = 0; i < 8; i++) {
        __nv_bfloat16 bh = __float2bfloat16_rn(xs[i]);
        float hf = __bfloat162float(bh);
        __nv_bfloat16 bl = __float2bfloat16_rn(xs[i] - hf);
        hs[i] = __bfloat16_as_ushort(bh);
        ls[i] = __bfloat16_as_ushort(bl);
    }
    uint4 H, L;
    H.x = (uint32_t)hs[0] | ((uint32_t)hs[1] << 16);
    H.y = (uint32_t)hs[2] | ((uint32_t)hs[3] << 16);
    H.z = (uint32_t)hs[4] | ((uint32_t)hs[5] << 16);
    H.w = (uint32_t)hs[6] | ((uint32_t)hs[7] << 16);
    L.x = (uint32_t)ls[0] | ((uint32_t)ls[1] << 16);
    L.y = (uint32_t)ls[2] | ((uint32_t)ls[3] << 16);
    L.z = (uint32_t)ls[4] | ((uint32_t)ls[5] << 16);
    L.w = (uint32_t)ls[6] | ((uint32_t)ls[7] << 16);
    *hi_dst = H;
    *lo_dst = L;
}

__global__ void k_convert_enc(const float* __restrict__ enc) {
    size_t t = (size_t)blockIdx.x * blockDim.x + threadIdx.x;   // 8M threads
    const float* p = enc + t * 8;
    float4 x0 = *(const float4*)p;
    float4 x1 = *(const float4*)(p + 4);
    float xs[8] = {x0.x, x0.y, x0.z, x0.w, x1.x, x1.y, x1.z, x1.w};
    split8_store(xs, &g_enc_hi4[t], &g_enc_lo4[t]);
}

__global__ void k_convert_We(const float* __restrict__ Wa) {
    int t  = blockIdx.x * blockDim.x + threadIdx.x;   // 128K threads
    int e  = t >> 7;
    int k0 = (t & 127) * 8;
    const float* p = Wa + (size_t)e * (2 * ND) + ND + k0;   // We[e, k]
    float4 x0 = *(const float4*)p;
    float4 x1 = *(const float4*)(p + 4);
    float xs[8] = {x0.x, x0.y, x0.z, x0.w, x1.x, x1.y, x1.z, x1.w};
    split8_store(xs, &g_We_hi4[t], &g_We_lo4[t]);
}

// ---------------------------------------------------------------------------
// dec_proj[b, e] = sum_k dec[b, k] * W_a[e, k]
// ---------------------------------------------------------------------------
__global__ void k_dec_proj(const float* __restrict__ dec,
                           const float* __restrict__ Wa) {
    __shared__ float ds[ND];
    const int b = blockIdx.x;
    for (int k = threadIdx.x; k < ND; k += blockDim.x)
        ds[k] = dec[b * ND + k];
    __syncthreads();

    const int warp = threadIdx.x >> 5;
    const int lane = threadIdx.x & 31;
    for (int el = warp; el < 128; el += 8) {
        const int e = blockIdx.y * 128 + el;
        const float* w = Wa + (size_t)e * (2 * ND);
        float s = 0.0f;
        for (int k = lane; k < ND; k += 32)
            s = fmaf(ds[k], w[k], s);
#pragma unroll
        for (int o = 16; o; o >>= 1)
            s += __shfl_xor_sync(0xffffffffu, s, o);
        if (lane == 0)
            g_dec_proj[b * ND + e] = s;
    }
}

// ---------------------------------------------------------------------------
// Main GEMM: mma.sync bf16 3-pass split + fused tanh/v epilogue.
// CTA 128(M) x 256(N), K chunks of 32, 3-stage cp.async pipeline.
// 512 threads = 16 warps as 4(m) x 4(n); warp tile 32(M) x 64(N).
// grid (nt=4, mt=512).
// ---------------------------------------------------------------------------
__global__ __launch_bounds__(GT, 1)
void k_gemm_tc(const float* __restrict__ v) {
    extern __shared__ __align__(16) char smem[];
    const uint32_t smem_base = smem_to_u32(smem);

    const int tid    = threadIdx.x;
    const int wid    = tid >> 5;
    const int lane   = tid & 31;
    const int warp_m = wid & 3;         // 0..3 -> m offset *32
    const int warp_n = wid >> 2;        // 0..3 -> n offset *64
    const int nt_blk = blockIdx.x;      // 0..3
    const int mt_blk = blockIdx.y;      // 0..511
    const int m0 = mt_blk * 128;
    const int n0 = nt_blk * 256;

    // Global bases (byte pointers), row-major bf16, row = 2048 B
    const char* gAh = (const char*)g_enc_hi4 + (size_t)m0 * 2048;
    const char* gAl = (const char*)g_enc_lo4 + (size_t)m0 * 2048;
    const char* gBh = (const char*)g_We_hi4 + (size_t)n0 * 2048;
    const char* gBl = (const char*)g_We_lo4 + (size_t)n0 * 2048;

    // Per-thread copy slots
    const int rcA = tid >> 2;                    // 0..127
    const int cc  = (tid & 3) * 16;              // 0,16,32,48
    const int rcB0 = tid >> 2;                   // 0..127
    const int rcB1 = (tid + GT) >> 2;            // 128..255

    const size_t soA  = (size_t)rcA * 2048 + cc;
    const size_t soB0 = (size_t)rcB0 * 2048 + cc;
    const size_t soB1 = (size_t)rcB1 * 2048 + cc;
    const uint32_t doA  = (uint32_t)(rcA * ROW_PITCH + cc);
    const uint32_t doB0 = (uint32_t)(rcB0 * ROW_PITCH + cc);
    const uint32_t doB1 = (uint32_t)(rcB1 * ROW_PITCH + cc);

    auto load_stage = [&](int stage, int kc) {
        const uint32_t sb = smem_base + stage * STAGE_BYTES;
        const size_t ko = (size_t)kc * 64;
        cp_async16(sb + doA,                        gAh + soA + ko);
        cp_async16(sb + TILE_A + doA,               gAl + soA + ko);
        cp_async16(sb + 2 * TILE_A + doB0,          gBh + soB0 + ko);
        cp_async16(sb + 2 * TILE_A + doB1,          gBh + soB1 + ko);
        cp_async16(sb + 2 * TILE_A + TILE_B + doB0, gBl + soB0 + ko);
        cp_async16(sb + 2 * TILE_A + TILE_B + doB1, gBl + soB1 + ko);
    };

    float acc[2][8][4];
#pragma unroll
    for (int mt = 0; mt < 2; mt++)
#pragma unroll
        for (int nt = 0; nt < 8; nt++)
#pragma unroll
            for (int i = 0; i < 4; i++)
                acc[mt][nt][i] = 0.0f;

    // ldmatrix lane-address components (bytes within a tile)
    const uint32_t a_row_l = (uint32_t)((lane & 7) + ((lane >> 3) & 1) * 8);
    const uint32_t a_kh_l  = (uint32_t)((lane >> 4) * 16);
    const uint32_t b_row_l = (uint32_t)(((lane >> 4) & 1) * 8 + (lane & 7));
    const uint32_t b_kh_l  = (uint32_t)(((lane >> 3) & 1) * 16);

    // Prologue: 2 stages in flight
    load_stage(0, 0); cp_commit();
    load_stage(1, 1); cp_commit();

    for (int kc = 0; kc < NKC; kc++) {
        if (kc + 2 < NKC) cp_wait1(); else cp_wait0();
        __syncthreads();

        if (kc + 2 < NKC) {
            load_stage((kc + 2) % N_STAGES, kc + 2);
            cp_commit();
        }

        const uint32_t sb  = smem_base + (kc % N_STAGES) * STAGE_BYTES;
        const uint32_t sbB = sb + 2 * TILE_A;
#pragma unroll
        for (int ks = 0; ks < 2; ks++) {
            const uint32_t kso = ks * 32;
            uint32_t aH[2][4], aL[2][4];
#pragma unroll
            for (int mt = 0; mt < 2; mt++) {
                const uint32_t rowoff =
                    (uint32_t)(warp_m * 32 + mt * 16) + a_row_l;
                const uint32_t off = rowoff * ROW_PITCH + kso + a_kh_l;
                ldmatrix_x4(aH[mt], sb + off);
                ldmatrix_x4(aL[mt], sb + TILE_A + off);
            }
#pragma unroll
            for (int half = 0; half < 2; half++) {
                uint32_t bH[4][2], bL[4][2];
#pragma unroll
                for (int q = 0; q < 2; q++) {
                    const uint32_t rowoff =
                        (uint32_t)(warp_n * 64 + (half * 2 + q) * 16) + b_row_l;
                    const uint32_t off = rowoff * ROW_PITCH + kso + b_kh_l;
                    uint32_t th[4], tl[4];
                    ldmatrix_x4(th, sbB + off);
                    ldmatrix_x4(tl, sbB + TILE_B + off);
                    bH[2 * q][0] = th[0]; bH[2 * q][1] = th[1];
                    bH[2 * q + 1][0] = th[2]; bH[2 * q + 1][1] = th[3];
                    bL[2 * q][0] = tl[0]; bL[2 * q][1] = tl[1];
                    bL[2 * q + 1][0] = tl[2]; bL[2 * q + 1][1] = tl[3];
                }
                // 3 passes: Ah*Bh + Ah*Bl + Al*Bh
#pragma unroll
                for (int mt = 0; mt < 2; mt++)
#pragma unroll
                    for (int nt = 0; nt < 4; nt++)
                        mma_bf16(acc[mt][half * 4 + nt], aH[mt], bH[nt]);
#pragma unroll
                for (int mt = 0; mt < 2; mt++)
#pragma unroll
                    for (int nt = 0; nt < 4; nt++)
                        mma_bf16(acc[mt][half * 4 + nt], aH[mt], bL[nt]);
#pragma unroll
                for (int mt = 0; mt < 2; mt++)
#pragma unroll
                    for (int nt = 0; nt < 4; nt++)
                        mma_bf16(acc[mt][half * 4 + nt], aL[mt], bH[nt]);
            }
        }
    }

    // ----- Fused epilogue: tanh(acc + dec_proj)*v, reduce over n -----
    const int b = m0 >> 11;   // 2048 rows per batch
    float dv[16], vv[16];
#pragma unroll
    for (int nt = 0; nt < 8; nt++)
#pragma unroll
        for (int c = 0; c < 2; c++) {
            const int col = n0 + warp_n * 64 + nt * 8 + (lane & 3) * 2 + c;
            dv[nt * 2 + c] = g_dec_proj[b * ND + col];
            vv[nt * 2 + c] = v[col];
        }

    float* red = (float*)smem;    // 128 rows x 4 warp_n floats
    __syncthreads();              // everyone done with mainloop smem

#pragma unroll
    for (int mt = 0; mt < 2; mt++)
#pragma unroll
        for (int h = 0; h < 2; h++) {
            float s = 0.0f;
#pragma unroll
            for (int nt = 0; nt < 8; nt++)
#pragma unroll
                for (int c = 0; c < 2; c++)
                    s = fmaf(tanh_acc(acc[mt][nt][h * 2 + c] + dv[nt * 2 + c]),
                             vv[nt * 2 + c], s);
            // reduce across the 4 lanes sharing this row
            s += __shfl_xor_sync(0xffffffffu, s, 1);
            s += __shfl_xor_sync(0xffffffffu, s, 2);
            if ((lane & 3) == 0) {
                const int lr = warp_m * 32 + mt * 16 + h * 8 + (lane >> 2);
                red[lr * 4 + warp_n] = s;
            }
        }
    __syncthreads();

    if (tid < 128) {
        const float* r = &red[tid * 4];
        g_partials[(size_t)(m0 + tid) * 4 + nt_blk] =
            (r[0] + r[1]) + (r[2] + r[3]);
    }
}

// ---------------------------------------------------------------------------
// Per-batch softmax over s
// ---------------------------------------------------------------------------
__global__ void k_softmax(float* __restrict__ out) {
    __shared__ float sc[NS];
    __shared__ float wred[8];
    const int b = blockIdx.x;
    const int tid = threadIdx.x;
    const int warp = tid >> 5, lane = tid & 31;

    float mx = -1e30f;
    for (int s = tid; s < NS; s += 256) {
        const float* p = &g_partials[((size_t)(b * NS + s)) * 4];
        float t = (p[0] + p[1]) + (p[2] + p[3]);
        sc[s] = t;
        mx = fmaxf(mx, t);
    }
#pragma unroll
    for (int o = 16; o; o >>= 1)
        mx = fmaxf(mx, __shfl_xor_sync(0xffffffffu, mx, o));
    if (lane == 0) wred[warp] = mx;
    __syncthreads();
    if (tid == 0) {
        float m = wred[0];
#pragma unroll
        for (int i = 1; i < 8; i++) m = fmaxf(m, wred[i]);
        wred[0] = m;
    }
    __syncthreads();
    const float bm = wred[0];
    __syncthreads();

    float sum = 0.0f;
    for (int s = tid; s < NS; s += 256) {
        float e = __expf(sc[s] - bm);
        sc[s] = e;
        sum += e;
    }
#pragma unroll
    for (int o = 16; o; o >>= 1)
        sum += __shfl_xor_sync(0xffffffffu, sum, o);
    if (lane == 0) wred[warp] = sum;
    __syncthreads();
    if (tid == 0) {
        float t = 0.0f;
#pragma unroll
        for (int i = 0; i < 8; i++) t += wred[i];
        wred[0] = t;
    }
    __syncthreads();
    const float inv = 1.0f / wred[0];
    for (int s = tid; s < NS; s += 256)
        out[b * NS + s] = sc[s] * inv;
}

// ---------------------------------------------------------------------------
// Launch
// ---------------------------------------------------------------------------
extern "C" void kernel_launch(void* const* d_in, const int* in_sizes, int n_in,
                              void* d_out, int out_size) {
    const float* dec = (const float*)d_in[0];
    const float* enc = (const float*)d_in[1];
    const float* Wa  = (const float*)d_in[2];
    const float* v   = (const float*)d_in[3];
    float* out = (float*)d_out;
    (void)in_sizes; (void)n_in; (void)out_size;

    cudaFuncSetAttribute(k_gemm_tc, cudaFuncAttributeMaxDynamicSharedMemorySize, SMEM_GEMM);

    k_convert_enc<<<32768, 256>>>(enc);               // 8M threads
    k_convert_We<<<512, 256>>>(Wa);                   // 128K threads
    k_dec_proj<<<dim3(NB, 8), 256>>>(dec, Wa);
    k_gemm_tc<<<dim3(NT_TILES, MT_TILES), GT, SMEM_GEMM>>>(v);
    k_softmax<<<NB, 256>>>(out);
}

// round 11
// speedup vs baseline: 2.7803x; 1.2170x over previous
#include <cuda_runtime.h>
#include <cuda_bf16.h>
#include <math.h>
#include <stdint.h>

// Problem constants
#define NB 32
#define NS 2048
#define ND 1024

// GEMM tiling: CTA 128(M) x 128(N), K chunks of 32, swizzled pitch-64 smem
#define MT_TILES 512          // 65536 / 128
#define NT_TILES 8            // 1024 / 128
#define NKC 32                // K chunks of 32 (K = 1024)
#define TILE_SM 8192          // 128 rows x 64 B (32 bf16), no padding (XOR swizzle)
#define STAGE_BYTES (4 * TILE_SM)            // Ah, Al, Bh, Bl = 32768
#define N_STAGES 3
#define SMEM_GEMM (N_STAGES * STAGE_BYTES)   // 98304 B -> 2 CTAs/SM
#define GT 256                               // 8 warps

// Swizzled byte offset of (row r, 16B-chunk c) within one tile
__device__ __forceinline__ uint32_t sw_off(uint32_t r, uint32_t c) {
    return r * 64u + ((c ^ ((r >> 1) & 3u)) * 16u);
}

// ---------------------------------------------------------------------------
// Device scratch (allocation is banned -> __device__ globals)
// ---------------------------------------------------------------------------
__device__ float g_dec_proj[NB * ND];                  // 128 KB
__device__ float g_partials[(size_t)NB * NS * 8];      // 2 MB
__device__ __align__(16) uint4 g_enc_hi4[8388608];     // 128 MB  [m][k/8]
__device__ __align__(16) uint4 g_enc_lo4[8388608];     // 128 MB
__device__ __align__(16) uint4 g_We_hi4[131072];       // 2 MB    [e][k/8]
__device__ __align__(16) uint4 g_We_lo4[131072];       // 2 MB

// ---------------------------------------------------------------------------
// PTX helpers (plain sm_80-era instructions; no 'a'-suffix features)
// ---------------------------------------------------------------------------
__device__ __forceinline__ uint32_t smem_to_u32(const void* p) {
    uint32_t a;
    asm("{ .reg .u64 t; cvta.to.shared.u64 t, %1; cvt.u32.u64 %0, t; }" : "=r"(a) : "l"(p));
    return a;
}
__device__ __forceinline__ void cp_async16(uint32_t dst, const void* src) {
    asm volatile("cp.async.cg.shared.global [%0], [%1], 16;" :: "r"(dst), "l"(src) : "memory");
}
__device__ __forceinline__ void cp_commit() {
    asm volatile("cp.async.commit_group;" ::: "memory");
}
__device__ __forceinline__ void cp_wait1() {
    asm volatile("cp.async.wait_group 1;" ::: "memory");
}
__device__ __forceinline__ void cp_wait0() {
    asm volatile("cp.async.wait_group 0;" ::: "memory");
}
__device__ __forceinline__ void ldmatrix_x4(uint32_t* r, uint32_t addr) {
    asm volatile("ldmatrix.sync.aligned.m8n8.x4.shared.b16 {%0,%1,%2,%3}, [%4];"
        : "=r"(r[0]), "=r"(r[1]), "=r"(r[2]), "=r"(r[3]) : "r"(addr));
}
__device__ __forceinline__ void mma_bf16(float* c, const uint32_t* a, const uint32_t* b) {
    asm volatile(
        "mma.sync.aligned.m16n8k16.row.col.f32.bf16.bf16.f32 "
        "{%0,%1,%2,%3}, {%4,%5,%6,%7}, {%8,%9}, {%0,%1,%2,%3};"
        : "+f"(c[0]), "+f"(c[1]), "+f"(c[2]), "+f"(c[3])
        : "r"(a[0]), "r"(a[1]), "r"(a[2]), "r"(a[3]), "r"(b[0]), "r"(b[1]));
}

// ---------------------------------------------------------------------------
// Accurate tanh (tanh.approx's ~1e-3 error would blow the budget)
// ---------------------------------------------------------------------------
__device__ __forceinline__ float tanh_acc(float x) {
    float ax = fabsf(x);
    float e  = __expf(-2.0f * ax);
    float t  = __fdividef(1.0f - e, 1.0f + e);
    return copysignf(t, x);
}

// ---------------------------------------------------------------------------
// Conversion: fp32 -> exact bf16 hi/lo split, plain row-major.
// ---------------------------------------------------------------------------
__device__ __forceinline__ void split8_store(const float* xs, uint4* hi_dst, uint4* lo_dst) {
    unsigned short hs[8], ls[8];
#pragma unroll
    for (int i = 0; i < 8; i++) {
        __nv_bfloat16 bh = __float2bfloat16_rn(xs[i]);
        float hf = __bfloat162float(bh);
        __nv_bfloat16 bl = __float2bfloat16_rn(xs[i] - hf);
        hs[i] = __bfloat16_as_ushort(bh);
        ls[i] = __bfloat16_as_ushort(bl);
    }
    uint4 H, L;
    H.x = (uint32_t)hs[0] | ((uint32_t)hs[1] << 16);
    H.y = (uint32_t)hs[2] | ((uint32_t)hs[3] << 16);
    H.z = (uint32_t)hs[4] | ((uint32_t)hs[5] << 16);
    H.w = (uint32_t)hs[6] | ((uint32_t)hs[7] << 16);
    L.x = (uint32_t)ls[0] | ((uint32_t)ls[1] << 16);
    L.y = (uint32_t)ls[2] | ((uint32_t)ls[3] << 16);
    L.z = (uint32_t)ls[4] | ((uint32_t)ls[5] << 16);
    L.w = (uint32_t)ls[6] | ((uint32_t)ls[7] << 16);
    *hi_dst = H;
    *lo_dst = L;
}

__global__ void k_convert_enc(const float* __restrict__ enc) {
    size_t t = (size_t)blockIdx.x * blockDim.x + threadIdx.x;   // 8M threads
    const float* p = enc + t * 8;
    float4 x0 = *(const float4*)p;
    float4 x1 = *(const float4*)(p + 4);
    float xs[8] = {x0.x, x0.y, x0.z, x0.w, x1.x, x1.y, x1.z, x1.w};
    split8_store(xs, &g_enc_hi4[t], &g_enc_lo4[t]);
}

__global__ void k_convert_We(const float* __restrict__ Wa) {
    int t  = blockIdx.x * blockDim.x + threadIdx.x;   // 128K threads
    int e  = t >> 7;
    int k0 = (t & 127) * 8;
    const float* p = Wa + (size_t)e * (2 * ND) + ND + k0;   // We[e, k]
    float4 x0 = *(const float4*)p;
    float4 x1 = *(const float4*)(p + 4);
    float xs[8] = {x0.x, x0.y, x0.z, x0.w, x1.x, x1.y, x1.z, x1.w};
    split8_store(xs, &g_We_hi4[t], &g_We_lo4[t]);
}

// ---------------------------------------------------------------------------
// dec_proj[b, e] = sum_k dec[b, k] * W_a[e, k]
// ---------------------------------------------------------------------------
__global__ void k_dec_proj(const float* __restrict__ dec,
                           const float* __restrict__ Wa) {
    __shared__ float ds[ND];
    const int b = blockIdx.x;
    for (int k = threadIdx.x; k < ND; k += blockDim.x)
        ds[k] = dec[b * ND + k];
    __syncthreads();

    const int warp = threadIdx.x >> 5;
    const int lane = threadIdx.x & 31;
    for (int el = warp; el < 128; el += 8) {
        const int e = blockIdx.y * 128 + el;
        const float* w = Wa + (size_t)e * (2 * ND);
        float s = 0.0f;
        for (int k = lane; k < ND; k += 32)
            s = fmaf(ds[k], w[k], s);
#pragma unroll
        for (int o = 16; o; o >>= 1)
            s += __shfl_xor_sync(0xffffffffu, s, o);
        if (lane == 0)
            g_dec_proj[b * ND + e] = s;
    }
}

// ---------------------------------------------------------------------------
// Main GEMM: mma.sync bf16 3-pass split + fused tanh/v epilogue.
// CTA 128(M) x 128(N), K chunks of 32, 3-stage cp.async pipeline,
// XOR-swizzled pitch-64 smem -> 96 KB/CTA -> 2 independent CTAs per SM
// (decorrelated __syncthreads so tensor units stay fed at chunk boundaries).
// 256 threads = 8 warps as 4(m) x 2(n); warp tile 32(M) x 64(N).
// ---------------------------------------------------------------------------
__global__ __launch_bounds__(GT, 2)
void k_gemm_tc(const float* __restrict__ v) {
    extern __shared__ __align__(16) char smem[];
    const uint32_t smem_base = smem_to_u32(smem);

    const int tid    = threadIdx.x;
    const int wid    = tid >> 5;
    const int lane   = tid & 31;
    const int warp_m = wid & 3;         // 0..3 -> m offset *32
    const int warp_n = wid >> 2;        // 0..1 -> n offset *64
    const int nt_blk = blockIdx.x;      // 0..7
    const int mt_blk = blockIdx.y;      // 0..511
    const int m0 = mt_blk * 128;
    const int n0 = nt_blk * 128;

    // Global bases (byte pointers), row-major bf16, row = 2048 B
    const char* gAh = (const char*)g_enc_hi4 + (size_t)m0 * 2048;
    const char* gAl = (const char*)g_enc_lo4 + (size_t)m0 * 2048;
    const char* gBh = (const char*)g_We_hi4 + (size_t)n0 * 2048;
    const char* gBl = (const char*)g_We_lo4 + (size_t)n0 * 2048;

    // Per-thread copy slots: 512 16B-chunks per tile, 2 per thread per tile
    const uint32_t rc0 = (uint32_t)(tid >> 2);        // 0..63
    const uint32_t rc1 = rc0 + 64;                    // 64..127
    const uint32_t cc  = (uint32_t)(tid & 3);         // chunk 0..3

    const size_t so0 = (size_t)rc0 * 2048 + cc * 16;
    const size_t so1 = (size_t)rc1 * 2048 + cc * 16;
    const uint32_t do0 = sw_off(rc0, cc);
    const uint32_t do1 = sw_off(rc1, cc);

    auto load_stage = [&](int stage, int kc) {
        const uint32_t sb = smem_base + stage * STAGE_BYTES;
        const size_t ko = (size_t)kc * 64;
        cp_async16(sb + do0,               gAh + so0 + ko);
        cp_async16(sb + do1,               gAh + so1 + ko);
        cp_async16(sb + TILE_SM + do0,     gAl + so0 + ko);
        cp_async16(sb + TILE_SM + do1,     gAl + so1 + ko);
        cp_async16(sb + 2 * TILE_SM + do0, gBh + so0 + ko);
        cp_async16(sb + 2 * TILE_SM + do1, gBh + so1 + ko);
        cp_async16(sb + 3 * TILE_SM + do0, gBl + so0 + ko);
        cp_async16(sb + 3 * TILE_SM + do1, gBl + so1 + ko);
    };

    float acc[2][8][4];
#pragma unroll
    for (int mt = 0; mt < 2; mt++)
#pragma unroll
        for (int nt = 0; nt < 8; nt++)
#pragma unroll
            for (int i = 0; i < 4; i++)
                acc[mt][nt][i] = 0.0f;

    // ldmatrix lane row/chunk components
    const uint32_t a_row_l = (uint32_t)((lane & 7) + ((lane >> 3) & 1) * 8);
    const uint32_t a_c_l   = (uint32_t)(lane >> 4);          // k-half chunk
    const uint32_t b_row_l = (uint32_t)(((lane >> 4) & 1) * 8 + (lane & 7));
    const uint32_t b_c_l   = (uint32_t)((lane >> 3) & 1);    // k-half chunk

    // Prologue: 2 stages in flight
    load_stage(0, 0); cp_commit();
    load_stage(1, 1); cp_commit();

    for (int kc = 0; kc < NKC; kc++) {
        if (kc + 2 < NKC) cp_wait1(); else cp_wait0();
        __syncthreads();

        if (kc + 2 < NKC) {
            load_stage((kc + 2) % N_STAGES, kc + 2);
            cp_commit();
        }

        const uint32_t sb = smem_base + (kc % N_STAGES) * STAGE_BYTES;
#pragma unroll
        for (int ks = 0; ks < 2; ks++) {
            const uint32_t kc2 = (uint32_t)(2 * ks);
            uint32_t aH[2][4], aL[2][4];
#pragma unroll
            for (int mt = 0; mt < 2; mt++) {
                const uint32_t ra = (uint32_t)(warp_m * 32 + mt * 16) + a_row_l;
                const uint32_t off = sw_off(ra, kc2 + a_c_l);
                ldmatrix_x4(aH[mt], sb + off);
                ldmatrix_x4(aL[mt], sb + TILE_SM + off);
            }
#pragma unroll
            for (int half = 0; half < 2; half++) {
                uint32_t bH[4][2], bL[4][2];
#pragma unroll
                for (int q = 0; q < 2; q++) {
                    const uint32_t rb =
                        (uint32_t)(warp_n * 64 + (half * 2 + q) * 16) + b_row_l;
                    const uint32_t off = sw_off(rb, kc2 + b_c_l);
                    uint32_t th[4], tl[4];
                    ldmatrix_x4(th, sb + 2 * TILE_SM + off);
                    ldmatrix_x4(tl, sb + 3 * TILE_SM + off);
                    bH[2 * q][0] = th[0]; bH[2 * q][1] = th[1];
                    bH[2 * q + 1][0] = th[2]; bH[2 * q + 1][1] = th[3];
                    bL[2 * q][0] = tl[0]; bL[2 * q][1] = tl[1];
                    bL[2 * q + 1][0] = tl[2]; bL[2 * q + 1][1] = tl[3];
                }
                // 3 passes: Ah*Bh + Ah*Bl + Al*Bh
#pragma unroll
                for (int mt = 0; mt < 2; mt++)
#pragma unroll
                    for (int nt = 0; nt < 4; nt++)
                        mma_bf16(acc[mt][half * 4 + nt], aH[mt], bH[nt]);
#pragma unroll
                for (int mt = 0; mt < 2; mt++)
#pragma unroll
                    for (int nt = 0; nt < 4; nt++)
                        mma_bf16(acc[mt][half * 4 + nt], aH[mt], bL[nt]);
#pragma unroll
                for (int mt = 0; mt < 2; mt++)
#pragma unroll
                    for (int nt = 0; nt < 4; nt++)
                        mma_bf16(acc[mt][half * 4 + nt], aL[mt], bH[nt]);
            }
        }
    }

    // ----- Fused epilogue: tanh(acc + dec_proj)*v, reduce over n -----
    const int b = m0 >> 11;   // 2048 rows per batch
    float dv[16], vv[16];
#pragma unroll
    for (int nt = 0; nt < 8; nt++)
#pragma unroll
        for (int c = 0; c < 2; c++) {
            const int col = n0 + warp_n * 64 + nt * 8 + (lane & 3) * 2 + c;
            dv[nt * 2 + c] = g_dec_proj[b * ND + col];
            vv[nt * 2 + c] = v[col];
        }

    float* red = (float*)smem;    // 128 rows x 2 warp_n floats
    __syncthreads();              // everyone done with mainloop smem

#pragma unroll
    for (int mt = 0; mt < 2; mt++)
#pragma unroll
        for (int h = 0; h < 2; h++) {
            float s = 0.0f;
#pragma unroll
            for (int nt = 0; nt < 8; nt++)
#pragma unroll
                for (int c = 0; c < 2; c++)
                    s = fmaf(tanh_acc(acc[mt][nt][h * 2 + c] + dv[nt * 2 + c]),
                             vv[nt * 2 + c], s);
            // reduce across the 4 lanes sharing this row
            s += __shfl_xor_sync(0xffffffffu, s, 1);
            s += __shfl_xor_sync(0xffffffffu, s, 2);
            if ((lane & 3) == 0) {
                const int lr = warp_m * 32 + mt * 16 + h * 8 + (lane >> 2);
                red[lr * 2 + warp_n] = s;
            }
        }
    __syncthreads();

    if (tid < 128)
        g_partials[(size_t)(m0 + tid) * 8 + nt_blk] = red[tid * 2] + red[tid * 2 + 1];
}

// ---------------------------------------------------------------------------
// Per-batch softmax over s
// ---------------------------------------------------------------------------
__global__ void k_softmax(float* __restrict__ out) {
    __shared__ float sc[NS];
    __shared__ float wred[8];
    const int b = blockIdx.x;
    const int tid = threadIdx.x;
    const int warp = tid >> 5, lane = tid & 31;

    float mx = -1e30f;
    for (int s = tid; s < NS; s += 256) {
        const float* p = &g_partials[((size_t)(b * NS + s)) * 8];
        float t = ((p[0] + p[1]) + (p[2] + p[3])) + ((p[4] + p[5]) + (p[6] + p[7]));
        sc[s] = t;
        mx = fmaxf(mx, t);
    }
#pragma unroll
    for (int o = 16; o; o >>= 1)
        mx = fmaxf(mx, __shfl_xor_sync(0xffffffffu, mx, o));
    if (lane == 0) wred[warp] = mx;
    __syncthreads();
    if (tid == 0) {
        float m = wred[0];
#pragma unroll
        for (int i = 1; i < 8; i++) m = fmaxf(m, wred[i]);
        wred[0] = m;
    }
    __syncthreads();
    const float bm = wred[0];
    __syncthreads();

    float sum = 0.0f;
    for (int s = tid; s < NS; s += 256) {
        float e = __expf(sc[s] - bm);
        sc[s] = e;
        sum += e;
    }
#pragma unroll
    for (int o = 16; o; o >>= 1)
        sum += __shfl_xor_sync(0xffffffffu, sum, o);
    if (lane == 0) wred[warp] = sum;
    __syncthreads();
    if (tid == 0) {
        float t = 0.0f;
#pragma unroll
        for (int i = 0; i < 8; i++) t += wred[i];
        wred[0] = t;
    }
    __syncthreads();
    const float inv = 1.0f / wred[0];
    for (int s = tid; s < NS; s += 256)
        out[b * NS + s] = sc[s] * inv;
}

// ---------------------------------------------------------------------------
// Launch
// ---------------------------------------------------------------------------
extern "C" void kernel_launch(void* const* d_in, const int* in_sizes, int n_in,
                              void* d_out, int out_size) {
    const float* dec = (const float*)d_in[0];
    const float* enc = (const float*)d_in[1];
    const float* Wa  = (const float*)d_in[2];
    const float* v   = (const float*)d_in[3];
    float* out = (float*)d_out;
    (void)in_sizes; (void)n_in; (void)out_size;

    cudaFuncSetAttribute(k_gemm_tc, cudaFuncAttributeMaxDynamicSharedMemorySize, SMEM_GEMM);

    k_convert_enc<<<32768, 256>>>(enc);               // 8M threads
    k_convert_We<<<512, 256>>>(Wa);                   // 128K threads
    k_dec_proj<<<dim3(NB, 8), 256>>>(dec, Wa);
    k_gemm_tc<<<dim3(NT_TILES, MT_TILES), GT, SMEM_GEMM>>>(v);
    k_softmax<<<NB, 256>>>(out);
}

// round 13
// speedup vs baseline: 2.9705x; 1.0684x over previous
#include <cuda_runtime.h>
#include <cuda_bf16.h>
#include <math.h>
#include <stdint.h>

// Problem constants
#define NB 32
#define NS 2048
#define ND 1024

// GEMM tiling: CTA 128(M) x 128(N), K chunks of 32, swizzled pitch-64 smem
#define MT_TILES 512          // 65536 / 128
#define NT_TILES 8            // 1024 / 128
#define NKC 32                // K chunks of 32 (K = 1024)
#define TILE_SM 8192          // 128 rows x 64 B (32 bf16), XOR swizzle, no padding
#define STAGE_BYTES (4 * TILE_SM)            // Ah, Al, Bh, Bl = 32768
#define N_STAGES 3
#define SMEM_STAGES (N_STAGES * STAGE_BYTES) // 98304
#define MB_OFF SMEM_STAGES                   // mbarriers after stage data
#define SMEM_GEMM (SMEM_STAGES + 64)         // 98368 B -> still 2 CTAs/SM
#define GT 256                               // 8 warps

// Swizzled byte offset of (row r, 16B-chunk c) within one tile
__device__ __forceinline__ uint32_t sw_off(uint32_t r, uint32_t c) {
    return r * 64u + ((c ^ ((r >> 1) & 3u)) * 16u);
}

// ---------------------------------------------------------------------------
// Device scratch (allocation is banned -> __device__ globals)
// ---------------------------------------------------------------------------
__device__ float g_dec_proj[NB * ND];                  // 128 KB
__device__ float g_partials[(size_t)NB * NS * 8];      // 2 MB
__device__ __align__(16) uint4 g_enc_hi4[8388608];     // 128 MB  [m][k/8]
__device__ __align__(16) uint4 g_enc_lo4[8388608];     // 128 MB
__device__ __align__(16) uint4 g_We_hi4[131072];       // 2 MB    [e][k/8]
__device__ __align__(16) uint4 g_We_lo4[131072];       // 2 MB

// ---------------------------------------------------------------------------
// PTX helpers (plain sm_80/sm_90 instructions; no 'a'-suffix features)
// ---------------------------------------------------------------------------
__device__ __forceinline__ uint32_t smem_to_u32(const void* p) {
    uint32_t a;
    asm("{ .reg .u64 t; cvta.to.shared.u64 t, %1; cvt.u32.u64 %0, t; }" : "=r"(a) : "l"(p));
    return a;
}
__device__ __forceinline__ void cp_async16(uint32_t dst, const void* src) {
    asm volatile("cp.async.cg.shared.global [%0], [%1], 16;" :: "r"(dst), "l"(src) : "memory");
}
// Bind this thread's outstanding cp.asyncs to an mbarrier.
// .noinc is load-bearing: the default form is count-neutral (inc-then-dec) and
// never trips a barrier pre-initialized with the thread count -> deadlock (R12).
__device__ __forceinline__ void cp_async_mbar_arrive(uint32_t mbar) {
    asm volatile("cp.async.mbarrier.arrive.noinc.shared::cta.b64 [%0];" :: "r"(mbar) : "memory");
}
#define MBARRIER_INIT(addr, cnt) \
    asm volatile("mbarrier.init.shared.b64 [%0], %1;" :: "r"((uint32_t)(addr)), "r"((uint32_t)(cnt)) : "memory")
#define MBARRIER_ARRIVE(addr) \
    asm volatile("mbarrier.arrive.shared.b64 _, [%0];" :: "r"((uint32_t)(addr)) : "memory")
#define MBARRIER_WAIT_PARITY(mbar_smem_addr, phase_parity) do { \
    uint32_t _mbar = (uint32_t)(mbar_smem_addr); \
    uint32_t _parity = (uint32_t)(phase_parity); \
    uint32_t _done; \
    asm volatile("{\n\t.reg .pred p;\n\t" \
        "mbarrier.try_wait.parity.acquire.cta.shared::cta.b64 p, [%1], %2;\n\t" \
        "selp.b32 %0, 1, 0, p;\n\t}" : "=r"(_done) : "r"(_mbar), "r"(_parity) : "memory"); \
    if (!_done) { \
        asm volatile("{\n\t.reg .pred P1;\n\t" \
            "WAIT_LOOP_%=:\n\t" \
            "mbarrier.try_wait.parity.acquire.cta.shared::cta.b64 P1, [%0], %1, 0x989680;\n\t" \
            "@P1 bra.uni WAIT_DONE_%=;\n\t" \
            "bra.uni WAIT_LOOP_%=;\n\t" \
            "WAIT_DONE_%=:\n\t}" :: "r"(_mbar), "r"(_parity) : "memory"); \
    } \
} while (0)
__device__ __forceinline__ void ldmatrix_x4(uint32_t* r, uint32_t addr) {
    asm volatile("ldmatrix.sync.aligned.m8n8.x4.shared.b16 {%0,%1,%2,%3}, [%4];"
        : "=r"(r[0]), "=r"(r[1]), "=r"(r[2]), "=r"(r[3]) : "r"(addr));
}
__device__ __forceinline__ void mma_bf16(float* c, const uint32_t* a, const uint32_t* b) {
    asm volatile(
        "mma.sync.aligned.m16n8k16.row.col.f32.bf16.bf16.f32 "
        "{%0,%1,%2,%3}, {%4,%5,%6,%7}, {%8,%9}, {%0,%1,%2,%3};"
        : "+f"(c[0]), "+f"(c[1]), "+f"(c[2]), "+f"(c[3])
        : "r"(a[0]), "r"(a[1]), "r"(a[2]), "r"(a[3]), "r"(b[0]), "r"(b[1]));
}

// ---------------------------------------------------------------------------
// Accurate tanh (tanh.approx's ~1e-3 error would blow the budget)
// ---------------------------------------------------------------------------
__device__ __forceinline__ float tanh_acc(float x) {
    float ax = fabsf(x);
    float e  = __expf(-2.0f * ax);
    float t  = __fdividef(1.0f - e, 1.0f + e);
    return copysignf(t, x);
}

// ---------------------------------------------------------------------------
// Conversion: fp32 -> exact bf16 hi/lo split, plain row-major.
// ---------------------------------------------------------------------------
__device__ __forceinline__ void split8_store(const float* xs, uint4* hi_dst, uint4* lo_dst) {
    unsigned short hs[8], ls[8];
#pragma unroll
    for (int i = 0; i < 8; i++) {
        __nv_bfloat16 bh = __float2bfloat16_rn(xs[i]);
        float hf = __bfloat162float(bh);
        __nv_bfloat16 bl = __float2bfloat16_rn(xs[i] - hf);
        hs[i] = __bfloat16_as_ushort(bh);
        ls[i] = __bfloat16_as_ushort(bl);
    }
    uint4 H, L;
    H.x = (uint32_t)hs[0] | ((uint32_t)hs[1] << 16);
    H.y = (uint32_t)hs[2] | ((uint32_t)hs[3] << 16);
    H.z = (uint32_t)hs[4] | ((uint32_t)hs[5] << 16);
    H.w = (uint32_t)hs[6] | ((uint32_t)hs[7] << 16);
    L.x = (uint32_t)ls[0] | ((uint32_t)ls[1] << 16);
    L.y = (uint32_t)ls[2] | ((uint32_t)ls[3] << 16);
    L.z = (uint32_t)ls[4] | ((uint32_t)ls[5] << 16);
    L.w = (uint32_t)ls[6] | ((uint32_t)ls[7] << 16);
    *hi_dst = H;
    *lo_dst = L;
}

__global__ void k_convert_enc(const float* __restrict__ enc) {
    size_t t = (size_t)blockIdx.x * blockDim.x + threadIdx.x;   // 8M threads
    const float* p = enc + t * 8;
    float4 x0 = *(const float4*)p;
    float4 x1 = *(const float4*)(p + 4);
    float xs[8] = {x0.x, x0.y, x0.z, x0.w, x1.x, x1.y, x1.z, x1.w};
    split8_store(xs, &g_enc_hi4[t], &g_enc_lo4[t]);
}

__global__ void k_convert_We(const float* __restrict__ Wa) {
    int t  = blockIdx.x * blockDim.x + threadIdx.x;   // 128K threads
    int e  = t >> 7;
    int k0 = (t & 127) * 8;
    const float* p = Wa + (size_t)e * (2 * ND) + ND + k0;   // We[e, k]
    float4 x0 = *(const float4*)p;
    float4 x1 = *(const float4*)(p + 4);
    float xs[8] = {x0.x, x0.y, x0.z, x0.w, x1.x, x1.y, x1.z, x1.w};
    split8_store(xs, &g_We_hi4[t], &g_We_lo4[t]);
}

// ---------------------------------------------------------------------------
// dec_proj[b, e] = sum_k dec[b, k] * W_a[e, k]
// grid (NB, 128), 256 threads: one warp per output element.
// ---------------------------------------------------------------------------
__global__ void k_dec_proj(const float* __restrict__ dec,
                           const float* __restrict__ Wa) {
    __shared__ float ds[ND];
    const int b = blockIdx.x;
    for (int k = threadIdx.x; k < ND; k += blockDim.x)
        ds[k] = dec[b * ND + k];
    __syncthreads();

    const int warp = threadIdx.x >> 5;
    const int lane = threadIdx.x & 31;
    const int e = blockIdx.y * 8 + warp;
    const float* w = Wa + (size_t)e * (2 * ND);
    float s = 0.0f;
#pragma unroll 8
    for (int k = lane; k < ND; k += 32)
        s = fmaf(ds[k], w[k], s);
#pragma unroll
    for (int o = 16; o; o >>= 1)
        s += __shfl_xor_sync(0xffffffffu, s, o);
    if (lane == 0)
        g_dec_proj[b * ND + e] = s;
}

// ---------------------------------------------------------------------------
// Main GEMM: mma.sync bf16 3-pass split + fused tanh/v epilogue.
// CTA 128(M) x 128(N), K chunks of 32, 3-stage mbarrier pipeline (no
// per-chunk __syncthreads -> warps free-run; a warp waits only for data).
// 256 threads = 8 warps as 4(m) x 2(n); warp tile 32(M) x 64(N). 2 CTAs/SM.
// ---------------------------------------------------------------------------
__global__ __launch_bounds__(GT, 2)
void k_gemm_tc(const float* __restrict__ v) {
    extern __shared__ __align__(16) char smem[];
    const uint32_t smem_base = smem_to_u32(smem);

    const int tid    = threadIdx.x;
    const int wid    = tid >> 5;
    const int lane   = tid & 31;
    const int warp_m = wid & 3;         // 0..3 -> m offset *32
    const int warp_n = wid >> 2;        // 0..1 -> n offset *64
    const int nt_blk = blockIdx.x;      // 0..7
    const int mt_blk = blockIdx.y;      // 0..511
    const int m0 = mt_blk * 128;
    const int n0 = nt_blk * 128;

    // mbarriers: full[s] fill-complete (256 .noinc cp.async completions),
    //            free[s] stage reusable (256 thread arrives)
    const uint32_t mb = smem_base + MB_OFF;
    if (tid == 0) {
#pragma unroll
        for (int s = 0; s < N_STAGES; s++) {
            MBARRIER_INIT(mb + s * 8, GT);        // full[s]
            MBARRIER_INIT(mb + 24 + s * 8, GT);   // free[s]
        }
    }
    __syncthreads();

    // Global bases (byte pointers), row-major bf16, row = 2048 B
    const char* gAh = (const char*)g_enc_hi4 + (size_t)m0 * 2048;
    const char* gAl = (const char*)g_enc_lo4 + (size_t)m0 * 2048;
    const char* gBh = (const char*)g_We_hi4 + (size_t)n0 * 2048;
    const char* gBl = (const char*)g_We_lo4 + (size_t)n0 * 2048;

    // Per-thread copy slots: 512 16B-chunks per tile, 2 per thread per tile
    const uint32_t rc0 = (uint32_t)(tid >> 2);        // 0..63
    const uint32_t rc1 = rc0 + 64;                    // 64..127
    const uint32_t cc  = (uint32_t)(tid & 3);         // chunk 0..3

    const size_t so0 = (size_t)rc0 * 2048 + cc * 16;
    const size_t so1 = (size_t)rc1 * 2048 + cc * 16;
    const uint32_t do0 = sw_off(rc0, cc);
    const uint32_t do1 = sw_off(rc1, cc);

    // Issue this thread's 8 copies for chunk kc into stage s, bind to full[s]
    auto load_chunk = [&](int stage, int kc) {
        const uint32_t sb = smem_base + stage * STAGE_BYTES;
        const size_t ko = (size_t)kc * 64;
        cp_async16(sb + do0,               gAh + so0 + ko);
        cp_async16(sb + do1,               gAh + so1 + ko);
        cp_async16(sb + TILE_SM + do0,     gAl + so0 + ko);
        cp_async16(sb + TILE_SM + do1,     gAl + so1 + ko);
        cp_async16(sb + 2 * TILE_SM + do0, gBh + so0 + ko);
        cp_async16(sb + 2 * TILE_SM + do1, gBh + so1 + ko);
        cp_async16(sb + 3 * TILE_SM + do0, gBl + so0 + ko);
        cp_async16(sb + 3 * TILE_SM + do1, gBl + so1 + ko);
        cp_async_mbar_arrive(mb + stage * 8);
    };

    float acc[2][8][4];
#pragma unroll
    for (int mt = 0; mt < 2; mt++)
#pragma unroll
        for (int nt = 0; nt < 8; nt++)
#pragma unroll
            for (int i = 0; i < 4; i++)
                acc[mt][nt][i] = 0.0f;

    // ldmatrix lane row/chunk components
    const uint32_t a_row_l = (uint32_t)((lane & 7) + ((lane >> 3) & 1) * 8);
    const uint32_t a_c_l   = (uint32_t)(lane >> 4);          // k-half chunk
    const uint32_t b_row_l = (uint32_t)(((lane >> 4) & 1) * 8 + (lane & 7));
    const uint32_t b_c_l   = (uint32_t)((lane >> 3) & 1);    // k-half chunk

    // Prologue: 2 chunks in flight
    load_chunk(0, 0);
    load_chunk(1, 1);

    for (int kc = 0; kc < NKC; kc++) {
        const int s = kc % N_STAGES;

        // Issue loads for kc+2 (WAR-guarded by free[(kc+2)%3], whose arrivals
        // came from the consumption of chunk kc-1 in that same stage).
        if (kc + 2 < NKC) {
            const int c2 = kc + 2;
            const int s2 = c2 % N_STAGES;
            if (c2 >= N_STAGES)
                MBARRIER_WAIT_PARITY(mb + 24 + s2 * 8, ((c2 - N_STAGES) / N_STAGES) & 1);
            load_chunk(s2, c2);
        }

        // Wait for this chunk's data (all 256 threads' copies complete)
        MBARRIER_WAIT_PARITY(mb + s * 8, (kc / N_STAGES) & 1);

        const uint32_t sb = smem_base + s * STAGE_BYTES;
#pragma unroll
        for (int ks = 0; ks < 2; ks++) {
            const uint32_t kc2 = (uint32_t)(2 * ks);
            uint32_t aH[2][4], aL[2][4];
#pragma unroll
            for (int mt = 0; mt < 2; mt++) {
                const uint32_t ra = (uint32_t)(warp_m * 32 + mt * 16) + a_row_l;
                const uint32_t off = sw_off(ra, kc2 + a_c_l);
                ldmatrix_x4(aH[mt], sb + off);
                ldmatrix_x4(aL[mt], sb + TILE_SM + off);
            }
#pragma unroll
            for (int half = 0; half < 2; half++) {
                uint32_t bH[4][2], bL[4][2];
#pragma unroll
                for (int q = 0; q < 2; q++) {
                    const uint32_t rb =
                        (uint32_t)(warp_n * 64 + (half * 2 + q) * 16) + b_row_l;
                    const uint32_t off = sw_off(rb, kc2 + b_c_l);
                    uint32_t th[4], tl[4];
                    ldmatrix_x4(th, sb + 2 * TILE_SM + off);
                    ldmatrix_x4(tl, sb + 3 * TILE_SM + off);
                    bH[2 * q][0] = th[0]; bH[2 * q][1] = th[1];
                    bH[2 * q + 1][0] = th[2]; bH[2 * q + 1][1] = th[3];
                    bL[2 * q][0] = tl[0]; bL[2 * q][1] = tl[1];
                    bL[2 * q + 1][0] = tl[2]; bL[2 * q + 1][1] = tl[3];
                }
                // 3 passes: Ah*Bh + Ah*Bl + Al*Bh
#pragma unroll
                for (int mt = 0; mt < 2; mt++)
#pragma unroll
                    for (int nt = 0; nt < 4; nt++)
                        mma_bf16(acc[mt][half * 4 + nt], aH[mt], bH[nt]);
#pragma unroll
                for (int mt = 0; mt < 2; mt++)
#pragma unroll
                    for (int nt = 0; nt < 4; nt++)
                        mma_bf16(acc[mt][half * 4 + nt], aH[mt], bL[nt]);
#pragma unroll
                for (int mt = 0; mt < 2; mt++)
#pragma unroll
                    for (int nt = 0; nt < 4; nt++)
                        mma_bf16(acc[mt][half * 4 + nt], aL[mt], bH[nt]);
            }
        }

        // Done reading stage s; release it for the kc+3 fill
        MBARRIER_ARRIVE(mb + 24 + s * 8);
    }

    // ----- Fused epilogue: tanh(acc + dec_proj)*v, reduce over n -----
    const int b = m0 >> 11;   // 2048 rows per batch
    float dv[16], vv[16];
#pragma unroll
    for (int nt = 0; nt < 8; nt++)
#pragma unroll
        for (int c = 0; c < 2; c++) {
            const int col = n0 + warp_n * 64 + nt * 8 + (lane & 3) * 2 + c;
            dv[nt * 2 + c] = g_dec_proj[b * ND + col];
            vv[nt * 2 + c] = v[col];
        }

    float* red = (float*)smem;    // 128 rows x 2 warp_n floats
    __syncthreads();              // all warps past their last smem reads

#pragma unroll
    for (int mt = 0; mt < 2; mt++)
#pragma unroll
        for (int h = 0; h < 2; h++) {
            float s = 0.0f;
#pragma unroll
            for (int nt = 0; nt < 8; nt++)
#pragma unroll
                for (int c = 0; c < 2; c++)
                    s = fmaf(tanh_acc(acc[mt][nt][h * 2 + c] + dv[nt * 2 + c]),
                             vv[nt * 2 + c], s);
            // reduce across the 4 lanes sharing this row
            s += __shfl_xor_sync(0xffffffffu, s, 1);
            s += __shfl_xor_sync(0xffffffffu, s, 2);
            if ((lane & 3) == 0) {
                const int lr = warp_m * 32 + mt * 16 + h * 8 + (lane >> 2);
                red[lr * 2 + warp_n] = s;
            }
        }
    __syncthreads();

    if (tid < 128)
        g_partials[(size_t)(m0 + tid) * 8 + nt_blk] = red[tid * 2] + red[tid * 2 + 1];
}

// ---------------------------------------------------------------------------
// Per-batch softmax over s
// ---------------------------------------------------------------------------
__global__ void k_softmax(float* __restrict__ out) {
    __shared__ float sc[NS];
    __shared__ float wred[8];
    const int b = blockIdx.x;
    const int tid = threadIdx.x;
    const int warp = tid >> 5, lane = tid & 31;

    float mx = -1e30f;
    for (int s = tid; s < NS; s += 256) {
        const float* p = &g_partials[((size_t)(b * NS + s)) * 8];
        float t = ((p[0] + p[1]) + (p[2] + p[3])) + ((p[4] + p[5]) + (p[6] + p[7]));
        sc[s] = t;
        mx = fmaxf(mx, t);
    }
#pragma unroll
    for (int o = 16; o; o >>= 1)
        mx = fmaxf(mx, __shfl_xor_sync(0xffffffffu, mx, o));
    if (lane == 0) wred[warp] = mx;
    __syncthreads();
    if (tid == 0) {
        float m = wred[0];
#pragma unroll
        for (int i = 1; i < 8; i++) m = fmaxf(m, wred[i]);
        wred[0] = m;
    }
    __syncthreads();
    const float bm = wred[0];
    __syncthreads();

    float sum = 0.0f;
    for (int s = tid; s < NS; s += 256) {
        float e = __expf(sc[s] - bm);
        sc[s] = e;
        sum += e;
    }
#pragma unroll
    for (int o = 16; o; o >>= 1)
        sum += __shfl_xor_sync(0xffffffffu, sum, o);
    if (lane == 0) wred[warp] = sum;
    __syncthreads();
    if (tid == 0) {
        float t = 0.0f;
#pragma unroll
        for (int i = 0; i < 8; i++) t += wred[i];
        wred[0] = t;
    }
    __syncthreads();
    const float inv = 1.0f / wred[0];
    for (int s = tid; s < NS; s += 256)
        out[b * NS + s] = sc[s] * inv;
}

// ---------------------------------------------------------------------------
// Launch
// ---------------------------------------------------------------------------
extern "C" void kernel_launch(void* const* d_in, const int* in_sizes, int n_in,
                              void* d_out, int out_size) {
    const float* dec = (const float*)d_in[0];
    const float* enc = (const float*)d_in[1];
    const float* Wa  = (const float*)d_in[2];
    const float* v   = (const float*)d_in[3];
    float* out = (float*)d_out;
    (void)in_sizes; (void)n_in; (void)out_size;

    cudaFuncSetAttribute(k_gemm_tc, cudaFuncAttributeMaxDynamicSharedMemorySize, SMEM_GEMM);

    k_convert_enc<<<32768, 256>>>(enc);               // 8M threads
    k_convert_We<<<512, 256>>>(Wa);                   // 128K threads
    k_dec_proj<<<dim3(NB, 128), 256>>>(dec, Wa);
    k_gemm_tc<<<dim3(NT_TILES, MT_TILES), GT, SMEM_GEMM>>>(v);
    k_softmax<<<NB, 256>>>(out);
}